// round 5
// baseline (speedup 1.0000x reference)
#include <cuda_runtime.h>
#include <math.h>
#include <stdint.h>

// Problem constants
#define NB   16
#define NL   511
#define NS   512
#define ND   1024
#define NHID 512
#define NDFF 2048
#define NEA  256
#define NNH  4
#define NHD  256   // head dim

// ---------------- device scratch ----------------
__device__ float g_h  [NB*NS*ND];
__device__ float g_mem[NB*NS*ND];
__device__ float g_qkv[NB*NS*3*ND];
__device__ float g_att[NB*NNH*NS*NS];
__device__ float g_ao [NB*NS*ND];
__device__ float g_ff [NB*NS*NDFF];
__device__ float g_p1 [NB*NS*NHID];

// ---------------- tf32 helpers ----------------
static __device__ __forceinline__ float2 split_tf32(float x) {
    uint32_t hb;
    asm("cvt.rna.tf32.f32 %0, %1;" : "=r"(hb) : "f"(x));
    float hi = __uint_as_float(hb);
    float lo = x - hi;
    uint32_t lb;
    asm("cvt.rna.tf32.f32 %0, %1;" : "=r"(lb) : "f"(lo));
    return make_float2(hi, __uint_as_float(lb));
}

static __device__ __forceinline__ void mma_tf32(float c[4],
    uint32_t a0, uint32_t a1, uint32_t a2, uint32_t a3,
    uint32_t b0, uint32_t b1)
{
    asm volatile(
        "mma.sync.aligned.m16n8k8.row.col.f32.tf32.tf32.f32 "
        "{%0,%1,%2,%3},{%4,%5,%6,%7},{%8,%9},{%0,%1,%2,%3};"
        : "+f"(c[0]), "+f"(c[1]), "+f"(c[2]), "+f"(c[3])
        : "r"(a0), "r"(a1), "r"(a2), "r"(a3), "r"(b0), "r"(b1));
}

// ---------------- tensor-core tiled GEMM -------------
// C[M,N] = act(alpha * A @ op(B) + bias) + resid   (fp32-equivalent precision
// via 3-term split-tf32 MMA). Tile 128x128, k-step 16, 8 warps (4M x 2N),
// warp tile 32x64, mma m16n8k8.
// TRANSB=true : op(B)=B^T, B is [N,K] row-major.  TRANSB=false: B is [K,N].
// Requires M%128==0, N%128==0, K%16==0 (true for all calls here).
template<bool TRANSB>
__global__ __launch_bounds__(256) void k_gemm(
    const float* __restrict__ A, int lda, long long strAb, long long strAh,
    const float* __restrict__ Bm, int ldb, long long strBb, long long strBh,
    float* __restrict__ C, int ldc, long long strCb, long long strCh,
    const float* __restrict__ bias,
    const float* __restrict__ resid,
    int M, int N, int K, int nh, float alpha, int act, int causal)
{
    int z = blockIdx.z;
    int zb = z / nh, zh = z % nh;
    A  += zb*strAb + zh*strAh;
    Bm += zb*strBb + zh*strBh;
    C  += zb*strCb + zh*strCh;

    int m0 = blockIdx.y * 128, n0 = blockIdx.x * 128;
    if (causal && n0 > m0) return;   // fully-masked tile

    __shared__ float2 As[16][132];
    __shared__ float2 Bs[16][132];

    int tid  = threadIdx.x;
    int lane = tid & 31;
    int wid  = tid >> 5;
    int wm = (wid & 3) * 32;     // warp row offset in tile
    int wn = (wid >> 2) * 64;    // warp col offset in tile
    int qr = lane >> 2;          // 0..7
    int qc = lane & 3;           // 0..3

    // loader indices
    int am  = tid >> 1;               // 0..127  (A row / B row when TRANSB)
    int akb = (tid & 1) * 8;          // 0 or 8  (k sub-offset)
    int bk  = tid >> 4;               // 0..15   (B k-row, non-T)
    int bn  = (tid & 15) * 4;         // 0..60   (B col base, non-T)

    const float* Ap = A + (long long)(m0 + am) * lda + akb;
    const float* Bp;
    if (TRANSB) Bp = Bm + (long long)(n0 + am) * ldb + akb;
    else        Bp = Bm + (long long)bk * ldb + n0 + bn;

    float c[2][8][4];
    #pragma unroll
    for (int i = 0; i < 2; i++)
        #pragma unroll
        for (int j = 0; j < 8; j++)
            #pragma unroll
            for (int t = 0; t < 4; t++) c[i][j][t] = 0.f;

    int itc = K >> 4;

    float4 a0r, a1r, b0r, b1r;
    // prefetch iter 0
    a0r = *(const float4*)(Ap);
    a1r = *(const float4*)(Ap + 4);
    if (TRANSB) {
        b0r = *(const float4*)(Bp);
        b1r = *(const float4*)(Bp + 4);
    } else {
        b0r = *(const float4*)(Bp);
        b1r = *(const float4*)(Bp + 64);
    }

    for (int it = 0; it < itc; it++) {
        // ---- store staged regs to smem with tf32 split ----
        As[akb+0][am] = split_tf32(a0r.x);
        As[akb+1][am] = split_tf32(a0r.y);
        As[akb+2][am] = split_tf32(a0r.z);
        As[akb+3][am] = split_tf32(a0r.w);
        As[akb+4][am] = split_tf32(a1r.x);
        As[akb+5][am] = split_tf32(a1r.y);
        As[akb+6][am] = split_tf32(a1r.z);
        As[akb+7][am] = split_tf32(a1r.w);
        if (TRANSB) {
            Bs[akb+0][am] = split_tf32(b0r.x);
            Bs[akb+1][am] = split_tf32(b0r.y);
            Bs[akb+2][am] = split_tf32(b0r.z);
            Bs[akb+3][am] = split_tf32(b0r.w);
            Bs[akb+4][am] = split_tf32(b1r.x);
            Bs[akb+5][am] = split_tf32(b1r.y);
            Bs[akb+6][am] = split_tf32(b1r.z);
            Bs[akb+7][am] = split_tf32(b1r.w);
        } else {
            Bs[bk][bn+0]  = split_tf32(b0r.x);
            Bs[bk][bn+1]  = split_tf32(b0r.y);
            Bs[bk][bn+2]  = split_tf32(b0r.z);
            Bs[bk][bn+3]  = split_tf32(b0r.w);
            Bs[bk][bn+64] = split_tf32(b1r.x);
            Bs[bk][bn+65] = split_tf32(b1r.y);
            Bs[bk][bn+66] = split_tf32(b1r.z);
            Bs[bk][bn+67] = split_tf32(b1r.w);
        }
        __syncthreads();

        // ---- prefetch next iter (latency hidden behind MMAs) ----
        if (it + 1 < itc) {
            Ap += 16;
            a0r = *(const float4*)(Ap);
            a1r = *(const float4*)(Ap + 4);
            if (TRANSB) {
                Bp += 16;
                b0r = *(const float4*)(Bp);
                b1r = *(const float4*)(Bp + 4);
            } else {
                Bp += (long long)16 * ldb;
                b0r = *(const float4*)(Bp);
                b1r = *(const float4*)(Bp + 64);
            }
        }

        // ---- compute: two k8 sub-steps ----
        #pragma unroll
        for (int sub = 0; sub < 2; sub++) {
            int kb = sub * 8;
            float2 af[2][4];
            #pragma unroll
            for (int mt = 0; mt < 2; mt++) {
                int r = wm + mt*16 + qr;
                af[mt][0] = As[kb+qc  ][r];
                af[mt][1] = As[kb+qc  ][r+8];
                af[mt][2] = As[kb+qc+4][r];
                af[mt][3] = As[kb+qc+4][r+8];
            }
            float2 bf[8][2];
            #pragma unroll
            for (int nt = 0; nt < 8; nt++) {
                int n = wn + nt*8 + qr;
                bf[nt][0] = Bs[kb+qc  ][n];
                bf[nt][1] = Bs[kb+qc+4][n];
            }
            #pragma unroll
            for (int mt = 0; mt < 2; mt++) {
                uint32_t ah0 = __float_as_uint(af[mt][0].x);
                uint32_t ah1 = __float_as_uint(af[mt][1].x);
                uint32_t ah2 = __float_as_uint(af[mt][2].x);
                uint32_t ah3 = __float_as_uint(af[mt][3].x);
                uint32_t al0 = __float_as_uint(af[mt][0].y);
                uint32_t al1 = __float_as_uint(af[mt][1].y);
                uint32_t al2 = __float_as_uint(af[mt][2].y);
                uint32_t al3 = __float_as_uint(af[mt][3].y);
                #pragma unroll
                for (int nt = 0; nt < 8; nt++) {
                    uint32_t bh0 = __float_as_uint(bf[nt][0].x);
                    uint32_t bh1 = __float_as_uint(bf[nt][1].x);
                    uint32_t bl0 = __float_as_uint(bf[nt][0].y);
                    uint32_t bl1 = __float_as_uint(bf[nt][1].y);
                    mma_tf32(c[mt][nt], ah0, ah1, ah2, ah3, bh0, bh1);
                    mma_tf32(c[mt][nt], ah0, ah1, ah2, ah3, bl0, bl1);
                    mma_tf32(c[mt][nt], al0, al1, al2, al3, bh0, bh1);
                }
            }
        }
        __syncthreads();
    }

    // ---- epilogue ----
    #pragma unroll
    for (int mt = 0; mt < 2; mt++) {
        #pragma unroll
        for (int half = 0; half < 2; half++) {
            long long row = m0 + wm + mt*16 + qr + half*8;
            #pragma unroll
            for (int nt = 0; nt < 8; nt++) {
                int col = n0 + wn + nt*8 + 2*qc;
                float v0 = c[mt][nt][half*2+0] * alpha;
                float v1 = c[mt][nt][half*2+1] * alpha;
                if (bias) { v0 += bias[col]; v1 += bias[col+1]; }
                if (act == 1) { v0 = fmaxf(v0, 0.f); v1 = fmaxf(v1, 0.f); }
                else if (act == 2) {
                    v0 = (v0 >= 0.f) ? v0 : 0.01f * v0;
                    v1 = (v1 >= 0.f) ? v1 : 0.01f * v1;
                }
                if (resid) {
                    float2 rv = *(const float2*)(resid + row*ldc + col);
                    v0 += rv.x; v1 += rv.y;
                }
                *(float2*)(C + row*ldc + col) = make_float2(v0, v1);
            }
        }
    }
}

// ---------------- softmax over rows of S=512 ----------------
__global__ __launch_bounds__(256) void k_softmax(float* __restrict__ att, int causal)
{
    int gid = blockIdx.x;                    // b*NNH*NS + h*NS + i
    int i = gid & (NS - 1);
    float* row = att + (long long)gid * NS;
    int len = causal ? (i + 1) : NS;
    int t = threadIdx.x;

    float v0 = (t       < len) ? row[t]       : -1e30f;
    float v1 = (t + 256 < len) ? row[t + 256] : -1e30f;

    __shared__ float red[8];
    float m = fmaxf(v0, v1);
    #pragma unroll
    for (int off = 16; off; off >>= 1) m = fmaxf(m, __shfl_xor_sync(0xFFFFFFFFu, m, off));
    if ((t & 31) == 0) red[t >> 5] = m;
    __syncthreads();
    float mm = red[0];
    #pragma unroll
    for (int w = 1; w < 8; w++) mm = fmaxf(mm, red[w]);
    __syncthreads();

    float e0 = (t       < len) ? __expf(v0 - mm) : 0.f;
    float e1 = (t + 256 < len) ? __expf(v1 - mm) : 0.f;
    float s = e0 + e1;
    #pragma unroll
    for (int off = 16; off; off >>= 1) s += __shfl_xor_sync(0xFFFFFFFFu, s, off);
    if ((t & 31) == 0) red[t >> 5] = s;
    __syncthreads();
    float ss = 0.f;
    #pragma unroll
    for (int w = 0; w < 8; w++) ss += red[w];
    float inv = 1.f / ss;

    row[t]       = e0 * inv;
    row[t + 256] = e1 * inv;
}

// ---------------- LayerNorm over D=1024 (in place) ----------------
__global__ __launch_bounds__(256) void k_ln(float* __restrict__ h,
                                            const float* __restrict__ w,
                                            const float* __restrict__ b)
{
    float* x = h + (long long)blockIdx.x * ND;
    int t = threadIdx.x;
    float v[4];
    float s = 0.f;
    #pragma unroll
    for (int k = 0; k < 4; k++) { v[k] = x[t + k*256]; s += v[k]; }

    __shared__ float red[8];
    #pragma unroll
    for (int off = 16; off; off >>= 1) s += __shfl_xor_sync(0xFFFFFFFFu, s, off);
    if ((t & 31) == 0) red[t >> 5] = s;
    __syncthreads();
    float sum = 0.f;
    #pragma unroll
    for (int w2 = 0; w2 < 8; w2++) sum += red[w2];
    float mean = sum * (1.f / ND);
    __syncthreads();

    float sq = 0.f;
    #pragma unroll
    for (int k = 0; k < 4; k++) { float d = v[k] - mean; sq += d*d; }
    #pragma unroll
    for (int off = 16; off; off >>= 1) sq += __shfl_xor_sync(0xFFFFFFFFu, sq, off);
    if ((t & 31) == 0) red[t >> 5] = sq;
    __syncthreads();
    float var = 0.f;
    #pragma unroll
    for (int w2 = 0; w2 < 8; w2++) var += red[w2];
    float rstd = rsqrtf(var * (1.f / ND) + 1e-5f);

    #pragma unroll
    for (int k = 0; k < 4; k++) {
        int j = t + k*256;
        x[j] = (v[k] - mean) * rstd * w[j] + b[j];
    }
}

// ---------------- input stage: h1 = leaky(t*w1 + b1) ----------------
__global__ void k_build_h1(const float* __restrict__ target,
                           const float* __restrict__ bos,
                           const float* __restrict__ w1,
                           const float* __restrict__ b1,
                           float* __restrict__ h1)
{
    int idx = blockIdx.x * blockDim.x + threadIdx.x;   // NB*NS*NHID
    int j = idx % NHID;
    int bs = idx / NHID;
    int s = bs % NS, bb = bs / NS;
    float t = (s == 0) ? bos[0] : target[bb*NL + s - 1];
    float v = t * w1[j] + b1[j];
    h1[idx] = (v >= 0.f) ? v : 0.01f * v;
}

// ---------------- fill tgt (+PE, +prev/cur) and mem ----------------
__global__ void k_fill(const float* __restrict__ gs,
                       const float* __restrict__ prev,
                       const float* __restrict__ cur,
                       float* __restrict__ h, float* __restrict__ mem)
{
    int idx = blockIdx.x * blockDim.x + threadIdx.x;   // NB*NS*ND
    int j = idx % ND;
    int bs = idx / ND;
    int s = bs % NS, bb = bs / NS;
    float hv, mv;
    if (j < NHID) {
        int jj = j & ~1;
        float div = expf(-logf(10000.f) * (float)jj / (float)NHID);
        float ang = (float)s * div;
        float pe = (j & 1) ? cosf(ang) : sinf(ang);
        hv = h[idx] + pe;
        mv = gs[(long long)bs * NHID + j];
    } else if (j < NHID + NEA) {
        float p = prev[bb*NEA + (j - NHID)];
        hv = p; mv = p;
    } else {
        float c = cur[bb*NEA + (j - NHID - NEA)];
        hv = c; mv = c;
    }
    h[idx] = hv;
    mem[idx] = mv;
}

// ---------------- output head: dot with proj_w2, mask ----------------
__global__ void k_final(const float* __restrict__ p1,
                        const float* __restrict__ w2,
                        const float* __restrict__ b2,
                        const int* __restrict__ basis,
                        float* __restrict__ out)
{
    int warp = (blockIdx.x * blockDim.x + threadIdx.x) >> 5;
    int lane = threadIdx.x & 31;
    if (warp >= NB * NL) return;
    int bb = warp / NL, l = warp % NL;
    const float* rowp = p1 + ((long long)bb * NS + l + 1) * NHID;
    float sum = 0.f;
    #pragma unroll 4
    for (int j = lane; j < NHID; j += 32) sum += rowp[j] * w2[j];
    #pragma unroll
    for (int off = 16; off; off >>= 1) sum += __shfl_xor_sync(0xFFFFFFFFu, sum, off);
    if (lane == 0)
        out[warp] = (l < basis[bb]) ? (sum + b2[0]) : 0.f;
}

// ---------------- host side ----------------
static void gemm_tn(const float* A, int lda, const float* W, int ldb,
                    float* C, int ldc, const float* bias, const float* resid,
                    int M, int N, int K, float alpha, int act)
{
    dim3 g(N / 128, M / 128, 1);
    k_gemm<true><<<g, 256>>>(A, lda, 0, 0, W, ldb, 0, 0, C, ldc, 0, 0,
                             bias, resid, M, N, K, 1, alpha, act, 0);
}

extern "C" void kernel_launch(void* const* d_in, const int* in_sizes, int n_in,
                              void* d_out, int out_size)
{
    const float* gs      = (const float*)d_in[0];
    const float* prev    = (const float*)d_in[1];
    const float* cur     = (const float*)d_in[2];
    const float* target  = (const float*)d_in[3];
    const float* bos     = (const float*)d_in[4];
    const float* inp_w1  = (const float*)d_in[5];
    const float* inp_b1  = (const float*)d_in[6];
    const float* inp_w2  = (const float*)d_in[7];
    const float* inp_b2  = (const float*)d_in[8];
    const float* sa_qkv_w = (const float*)d_in[9];
    const float* sa_qkv_b = (const float*)d_in[10];
    const float* sa_out_w = (const float*)d_in[11];
    const float* sa_out_b = (const float*)d_in[12];
    const float* ca_qkv_w = (const float*)d_in[13];
    const float* ca_qkv_b = (const float*)d_in[14];
    const float* ca_out_w = (const float*)d_in[15];
    const float* ca_out_b = (const float*)d_in[16];
    const float* ln_w    = (const float*)d_in[17];
    const float* ln_b    = (const float*)d_in[18];
    const float* ff_w1   = (const float*)d_in[19];
    const float* ff_b1   = (const float*)d_in[20];
    const float* ff_w2   = (const float*)d_in[21];
    const float* ff_b2   = (const float*)d_in[22];
    const float* proj_w1 = (const float*)d_in[23];
    const float* proj_b1 = (const float*)d_in[24];
    const float* proj_w2 = (const float*)d_in[25];
    const float* proj_b2 = (const float*)d_in[26];
    const int*   basis   = (const int*)d_in[27];
    float* out = (float*)d_out;

    float *h_, *mem_, *qkv_, *att_, *ao_, *ff_, *p1_;
    cudaGetSymbolAddress((void**)&h_,   g_h);
    cudaGetSymbolAddress((void**)&mem_, g_mem);
    cudaGetSymbolAddress((void**)&qkv_, g_qkv);
    cudaGetSymbolAddress((void**)&att_, g_att);
    cudaGetSymbolAddress((void**)&ao_,  g_ao);
    cudaGetSymbolAddress((void**)&ff_,  g_ff);
    cudaGetSymbolAddress((void**)&p1_,  g_p1);

    const int M = NB * NS;         // 8192 tokens
    const float isq = 1.f / 16.f;  // 1/sqrt(256)

    // ---- input stage ----
    k_build_h1<<<(NB*NS*NHID)/256, 256>>>(target, bos, inp_w1, inp_b1, p1_);
    gemm_tn(p1_, NHID, inp_w2, NHID, h_, ND, inp_b2, nullptr, M, NHID, NHID, 1.f, 0);
    k_fill<<<(NB*NS*ND)/256, 256>>>(gs, prev, cur, h_, mem_);

    for (int l = 0; l < 3; l++) {
        const float* qkvw = sa_qkv_w + (long long)l * 3*ND*ND;
        const float* qkvb = sa_qkv_b + l * 3*ND;
        const float* ow   = sa_out_w + (long long)l * ND*ND;
        const float* ob   = sa_out_b + l * ND;

        // ===== self-attention (causal) =====
        gemm_tn(h_, ND, qkvw, ND, qkv_, 3*ND, qkvb, nullptr, M, 3*ND, ND, 1.f, 0);
        {
            dim3 g(NS/128, NS/128, NB*NNH);
            k_gemm<true><<<g, 256>>>(qkv_, 3*ND, (long long)NS*3*ND, NHD,
                                     qkv_ + ND, 3*ND, (long long)NS*3*ND, NHD,
                                     att_, NS, (long long)NNH*NS*NS, (long long)NS*NS,
                                     nullptr, nullptr, NS, NS, NHD, NNH, isq, 0, 1);
        }
        k_softmax<<<NB*NNH*NS, 256>>>(att_, 1);
        {
            dim3 g(NHD/128, NS/128, NB*NNH);
            k_gemm<false><<<g, 256>>>(att_, NS, (long long)NNH*NS*NS, (long long)NS*NS,
                                      qkv_ + 2*ND, 3*ND, (long long)NS*3*ND, NHD,
                                      ao_, ND, (long long)NS*ND, NHD,
                                      nullptr, nullptr, NS, NHD, NS, NNH, 1.f, 0, 0);
        }
        gemm_tn(ao_, ND, ow, ND, h_, ND, ob, h_, M, ND, ND, 1.f, 0);
        k_ln<<<M, 256>>>(h_, ln_w + (l*3 + 0)*ND, ln_b + (l*3 + 0)*ND);

        // ===== cross-attention =====
        qkvw = ca_qkv_w + (long long)l * 3*ND*ND;
        qkvb = ca_qkv_b + l * 3*ND;
        ow   = ca_out_w + (long long)l * ND*ND;
        ob   = ca_out_b + l * ND;
        gemm_tn(h_,   ND, qkvw,           ND, qkv_,      3*ND, qkvb,      nullptr, M,   ND, ND, 1.f, 0);
        gemm_tn(mem_, ND, qkvw + ND*ND,   ND, qkv_ + ND, 3*ND, qkvb + ND, nullptr, M, 2*ND, ND, 1.f, 0);
        {
            dim3 g(NS/128, NS/128, NB*NNH);
            k_gemm<true><<<g, 256>>>(qkv_, 3*ND, (long long)NS*3*ND, NHD,
                                     qkv_ + ND, 3*ND, (long long)NS*3*ND, NHD,
                                     att_, NS, (long long)NNH*NS*NS, (long long)NS*NS,
                                     nullptr, nullptr, NS, NS, NHD, NNH, isq, 0, 0);
        }
        k_softmax<<<NB*NNH*NS, 256>>>(att_, 0);
        {
            dim3 g(NHD/128, NS/128, NB*NNH);
            k_gemm<false><<<g, 256>>>(att_, NS, (long long)NNH*NS*NS, (long long)NS*NS,
                                      qkv_ + 2*ND, 3*ND, (long long)NS*3*ND, NHD,
                                      ao_, ND, (long long)NS*ND, NHD,
                                      nullptr, nullptr, NS, NHD, NS, NNH, 1.f, 0, 0);
        }
        gemm_tn(ao_, ND, ow, ND, h_, ND, ob, h_, M, ND, ND, 1.f, 0);
        k_ln<<<M, 256>>>(h_, ln_w + (l*3 + 1)*ND, ln_b + (l*3 + 1)*ND);

        // ===== feed-forward =====
        gemm_tn(h_, ND, ff_w1 + (long long)l*NDFF*ND, ND, ff_, NDFF,
                ff_b1 + l*NDFF, nullptr, M, NDFF, ND, 1.f, 1);
        gemm_tn(ff_, NDFF, ff_w2 + (long long)l*ND*NDFF, NDFF, h_, ND,
                ff_b2 + l*ND, h_, M, ND, NDFF, 1.f, 0);
        k_ln<<<M, 256>>>(h_, ln_w + (l*3 + 2)*ND, ln_b + (l*3 + 2)*ND);
    }

    // ---- output head ----
    gemm_tn(h_, ND, proj_w1, ND, p1_, NHID, proj_b1, nullptr, M, NHID, ND, 1.f, 2);
    k_final<<<(NB*NL*32 + 255)/256, 256>>>(p1_, proj_w2, proj_b2, basis, out);
}

// round 7
// speedup vs baseline: 2.8651x; 2.8651x over previous
#include <cuda_runtime.h>
#include <cuda_bf16.h>
#include <math.h>
#include <stdint.h>

// Problem constants
#define NB   16
#define NL   511
#define NS   512
#define ND   1024
#define NHID 512
#define NDFF 2048
#define NEA  256
#define NNH  4
#define NHD  256   // head dim

// ---------------- device scratch ----------------
__device__ float g_h  [NB*NS*ND];
__device__ float g_mem[NB*NS*ND];
__device__ float g_qkv[NB*NS*3*ND];
__device__ float g_att[NB*NNH*NS*NS];
__device__ float g_ao [NB*NS*ND];
__device__ float g_ff [NB*NS*NDFF];
__device__ float g_p1 [NB*NS*NHID];

// ---------------- helpers ----------------
static __device__ __forceinline__ void split_pack2(float x0, float x1,
                                                   uint32_t &h, uint32_t &l)
{
    __nv_bfloat16 h0 = __float2bfloat16_rn(x0);
    __nv_bfloat16 h1 = __float2bfloat16_rn(x1);
    __nv_bfloat16 l0 = __float2bfloat16_rn(x0 - __bfloat162float(h0));
    __nv_bfloat16 l1 = __float2bfloat16_rn(x1 - __bfloat162float(h1));
    h = ((uint32_t)__bfloat16_as_ushort(h1) << 16) | (uint32_t)__bfloat16_as_ushort(h0);
    l = ((uint32_t)__bfloat16_as_ushort(l1) << 16) | (uint32_t)__bfloat16_as_ushort(l0);
}

static __device__ __forceinline__ void split8(const float4 &u, const float4 &v,
                                              uint4 &H, uint4 &L)
{
    split_pack2(u.x, u.y, H.x, L.x);
    split_pack2(u.z, u.w, H.y, L.y);
    split_pack2(v.x, v.y, H.z, L.z);
    split_pack2(v.z, v.w, H.w, L.w);
}

static __device__ __forceinline__ void mma_bf16(float c[4],
    const uint32_t a[4], const uint32_t b[2])
{
    asm volatile(
        "mma.sync.aligned.m16n8k16.row.col.f32.bf16.bf16.f32 "
        "{%0,%1,%2,%3},{%4,%5,%6,%7},{%8,%9},{%0,%1,%2,%3};"
        : "+f"(c[0]), "+f"(c[1]), "+f"(c[2]), "+f"(c[3])
        : "r"(a[0]), "r"(a[1]), "r"(a[2]), "r"(a[3]), "r"(b[0]), "r"(b[1]));
}

static __device__ __forceinline__ void ldsm4(uint32_t &r0, uint32_t &r1,
                                             uint32_t &r2, uint32_t &r3, uint32_t a)
{
    asm volatile("ldmatrix.sync.aligned.m8n8.x4.shared.b16 {%0,%1,%2,%3},[%4];"
        : "=r"(r0), "=r"(r1), "=r"(r2), "=r"(r3) : "r"(a));
}

static __device__ __forceinline__ void ldsm4t(uint32_t &r0, uint32_t &r1,
                                              uint32_t &r2, uint32_t &r3, uint32_t a)
{
    asm volatile("ldmatrix.sync.aligned.m8n8.x4.trans.shared.b16 {%0,%1,%2,%3},[%4];"
        : "=r"(r0), "=r"(r1), "=r"(r2), "=r"(r3) : "r"(a));
}

// ---------------- tensor-core tiled GEMM (bf16x3 emulated fp32) -------------
// C[M,N] = act(alpha * A @ op(B) + bias) + resid
// Split each fp32 operand into hi+lo bf16; accumulate hi*hi + hi*lo + lo*hi
// with m16n8k16 bf16 MMAs (fp32 accumulators). Tile 128x128, k-step 16,
// 8 warps (4M x 2N), warp tile 32x64. Fragments loaded via ldmatrix with
// loop-invariant precomputed addresses.
// TRANSB=true : op(B)=B^T, B is [N,K] row-major.  TRANSB=false: B is [K,N].
// Requires M%128==0, N%128==0, K%16==0.
template<bool TRANSB>
__global__ __launch_bounds__(256) void k_gemm(
    const float* __restrict__ A, int lda, long long strAb, long long strAh,
    const float* __restrict__ Bm, int ldb, long long strBb, long long strBh,
    float* __restrict__ C, int ldc, long long strCb, long long strCh,
    const float* __restrict__ bias,
    const float* __restrict__ resid,
    int M, int N, int K, int nh, float alpha, int act, int causal)
{
    int z = blockIdx.z;
    int zb = z / nh, zh = z % nh;
    A  += zb*strAb + zh*strAh;
    Bm += zb*strBb + zh*strBh;
    C  += zb*strCb + zh*strCh;

    int m0 = blockIdx.y * 128, n0 = blockIdx.x * 128;
    if (causal && n0 > m0) return;   // fully-masked tile

    // A tiles: 128 rows x 16 k, pitch 24 elems (48B) -> conflict-free LDSM
    __shared__ __nv_bfloat16 AsH[128*24], AsL[128*24];
    constexpr int BROWS  = TRANSB ? 128 : 16;
    constexpr int BPITCH = TRANSB ? 24  : 136;   // 136 elems (272B) conflict-free
    __shared__ __nv_bfloat16 BsH[BROWS*BPITCH], BsL[BROWS*BPITCH];

    int tid  = threadIdx.x;
    int lane = tid & 31;
    int wid  = tid >> 5;
    int wm = (wid & 3) * 32;     // warp row offset in tile
    int wn = (wid >> 2) * 64;    // warp col offset in tile
    int qr = lane >> 2;          // 0..7
    int qc = lane & 3;           // 0..3

    // loader indices
    int arow = tid >> 1;             // 0..127 (A row; B n-row when TRANSB)
    int akh  = (tid & 1) * 8;        // k sub-offset 0/8
    int bkr  = tid >> 4;             // 0..15 (B k-row, non-T)
    int bnc  = (tid & 15) * 8;       // 0..120 (B col base, non-T)

    const float* Ap = A + (long long)(m0 + arow) * lda + akh;
    const float* Bp;
    if (TRANSB) Bp = Bm + (long long)(n0 + arow) * ldb + akh;
    else        Bp = Bm + (long long)bkr * ldb + n0 + bnc;

    // precomputed ldmatrix byte offsets (loop-invariant)
    uint32_t baseAH = (uint32_t)__cvta_generic_to_shared(AsH);
    uint32_t baseAL = (uint32_t)__cvta_generic_to_shared(AsL);
    uint32_t baseBH = (uint32_t)__cvta_generic_to_shared(BsH);
    uint32_t baseBL = (uint32_t)__cvta_generic_to_shared(BsL);

    uint32_t aoff[2];
    #pragma unroll
    for (int mt = 0; mt < 2; mt++)
        aoff[mt] = (uint32_t)(((wm + mt*16 + (lane & 15)) * 24 + ((lane >> 4) << 3)) * 2);

    uint32_t boff[4];
    #pragma unroll
    for (int p = 0; p < 4; p++) {
        if (TRANSB) {
            int r  = wn + p*16 + ((lane >> 4) << 3) + (lane & 7);
            int kh = ((lane >> 3) & 1) << 3;
            boff[p] = (uint32_t)((r * 24 + kh) * 2);
        } else {
            int rk = (((lane >> 3) & 1) << 3) + (lane & 7);
            int cn = wn + p*16 + ((lane >> 4) << 3);
            boff[p] = (uint32_t)((rk * 136 + cn) * 2);
        }
    }

    float c[2][8][4];
    #pragma unroll
    for (int i = 0; i < 2; i++)
        #pragma unroll
        for (int j = 0; j < 8; j++)
            #pragma unroll
            for (int t = 0; t < 4; t++) c[i][j][t] = 0.f;

    int itc = K >> 4;

    float4 a0r, a1r, b0r, b1r;
    a0r = *(const float4*)(Ap);
    a1r = *(const float4*)(Ap + 4);
    b0r = *(const float4*)(Bp);
    b1r = *(const float4*)(Bp + 4);

    for (int it = 0; it < itc; it++) {
        // ---- convert + store staged regs to smem ----
        {
            uint4 H, L;
            split8(a0r, a1r, H, L);
            *(uint4*)((char*)AsH + (arow*24 + akh)*2) = H;
            *(uint4*)((char*)AsL + (arow*24 + akh)*2) = L;
            split8(b0r, b1r, H, L);
            if (TRANSB) {
                *(uint4*)((char*)BsH + (arow*24 + akh)*2) = H;
                *(uint4*)((char*)BsL + (arow*24 + akh)*2) = L;
            } else {
                *(uint4*)((char*)BsH + (bkr*136 + bnc)*2) = H;
                *(uint4*)((char*)BsL + (bkr*136 + bnc)*2) = L;
            }
        }
        __syncthreads();

        // ---- prefetch next iter ----
        if (it + 1 < itc) {
            Ap += 16;
            a0r = *(const float4*)(Ap);
            a1r = *(const float4*)(Ap + 4);
            if (TRANSB) {
                Bp += 16;
            } else {
                Bp += (long long)16 * ldb;
            }
            b0r = *(const float4*)(Bp);
            b1r = *(const float4*)(Bp + 4);
        }

        // ---- load fragments via ldmatrix ----
        uint32_t aH[2][4], aL[2][4];
        #pragma unroll
        for (int mt = 0; mt < 2; mt++) {
            ldsm4(aH[mt][0], aH[mt][1], aH[mt][2], aH[mt][3], baseAH + aoff[mt]);
            ldsm4(aL[mt][0], aL[mt][1], aL[mt][2], aL[mt][3], baseAL + aoff[mt]);
        }
        uint32_t bH[8][2], bL[8][2];
        #pragma unroll
        for (int p = 0; p < 4; p++) {
            uint32_t r0, r1, r2, r3;
            if (TRANSB) ldsm4 (r0, r1, r2, r3, baseBH + boff[p]);
            else        ldsm4t(r0, r1, r2, r3, baseBH + boff[p]);
            bH[2*p][0] = r0; bH[2*p][1] = r1; bH[2*p+1][0] = r2; bH[2*p+1][1] = r3;
            if (TRANSB) ldsm4 (r0, r1, r2, r3, baseBL + boff[p]);
            else        ldsm4t(r0, r1, r2, r3, baseBL + boff[p]);
            bL[2*p][0] = r0; bL[2*p][1] = r1; bL[2*p+1][0] = r2; bL[2*p+1][1] = r3;
        }

        // ---- MMAs: hi*hi + hi*lo + lo*hi ----
        #pragma unroll
        for (int mt = 0; mt < 2; mt++) {
            #pragma unroll
            for (int nt = 0; nt < 8; nt++) {
                mma_bf16(c[mt][nt], aH[mt], bH[nt]);
                mma_bf16(c[mt][nt], aH[mt], bL[nt]);
                mma_bf16(c[mt][nt], aL[mt], bH[nt]);
            }
        }
        __syncthreads();
    }

    // ---- epilogue ----
    #pragma unroll
    for (int mt = 0; mt < 2; mt++) {
        #pragma unroll
        for (int half = 0; half < 2; half++) {
            long long row = m0 + wm + mt*16 + qr + half*8;
            #pragma unroll
            for (int nt = 0; nt < 8; nt++) {
                int col = n0 + wn + nt*8 + 2*qc;
                float v0 = c[mt][nt][half*2+0] * alpha;
                float v1 = c[mt][nt][half*2+1] * alpha;
                if (bias) { v0 += bias[col]; v1 += bias[col+1]; }
                if (act == 1) { v0 = fmaxf(v0, 0.f); v1 = fmaxf(v1, 0.f); }
                else if (act == 2) {
                    v0 = (v0 >= 0.f) ? v0 : 0.01f * v0;
                    v1 = (v1 >= 0.f) ? v1 : 0.01f * v1;
                }
                if (resid) {
                    float2 rv = *(const float2*)(resid + row*ldc + col);
                    v0 += rv.x; v1 += rv.y;
                }
                *(float2*)(C + row*ldc + col) = make_float2(v0, v1);
            }
        }
    }
}

// ---------------- softmax over rows of S=512 ----------------
__global__ __launch_bounds__(256) void k_softmax(float* __restrict__ att, int causal)
{
    int gid = blockIdx.x;                    // b*NNH*NS + h*NS + i
    int i = gid & (NS - 1);
    float* row = att + (long long)gid * NS;
    int len = causal ? (i + 1) : NS;
    int t = threadIdx.x;

    float v0 = (t       < len) ? row[t]       : -1e30f;
    float v1 = (t + 256 < len) ? row[t + 256] : -1e30f;

    __shared__ float red[8];
    float m = fmaxf(v0, v1);
    #pragma unroll
    for (int off = 16; off; off >>= 1) m = fmaxf(m, __shfl_xor_sync(0xFFFFFFFFu, m, off));
    if ((t & 31) == 0) red[t >> 5] = m;
    __syncthreads();
    float mm = red[0];
    #pragma unroll
    for (int w = 1; w < 8; w++) mm = fmaxf(mm, red[w]);
    __syncthreads();

    float e0 = (t       < len) ? __expf(v0 - mm) : 0.f;
    float e1 = (t + 256 < len) ? __expf(v1 - mm) : 0.f;
    float s = e0 + e1;
    #pragma unroll
    for (int off = 16; off; off >>= 1) s += __shfl_xor_sync(0xFFFFFFFFu, s, off);
    if ((t & 31) == 0) red[t >> 5] = s;
    __syncthreads();
    float ss = 0.f;
    #pragma unroll
    for (int w = 0; w < 8; w++) ss += red[w];
    float inv = 1.f / ss;

    row[t]       = e0 * inv;
    row[t + 256] = e1 * inv;
}

// ---------------- LayerNorm over D=1024 (in place) ----------------
__global__ __launch_bounds__(256) void k_ln(float* __restrict__ h,
                                            const float* __restrict__ w,
                                            const float* __restrict__ b)
{
    float* x = h + (long long)blockIdx.x * ND;
    int t = threadIdx.x;
    float v[4];
    float s = 0.f;
    #pragma unroll
    for (int k = 0; k < 4; k++) { v[k] = x[t + k*256]; s += v[k]; }

    __shared__ float red[8];
    #pragma unroll
    for (int off = 16; off; off >>= 1) s += __shfl_xor_sync(0xFFFFFFFFu, s, off);
    if ((t & 31) == 0) red[t >> 5] = s;
    __syncthreads();
    float sum = 0.f;
    #pragma unroll
    for (int w2 = 0; w2 < 8; w2++) sum += red[w2];
    float mean = sum * (1.f / ND);
    __syncthreads();

    float sq = 0.f;
    #pragma unroll
    for (int k = 0; k < 4; k++) { float d = v[k] - mean; sq += d*d; }
    #pragma unroll
    for (int off = 16; off; off >>= 1) sq += __shfl_xor_sync(0xFFFFFFFFu, sq, off);
    if ((t & 31) == 0) red[t >> 5] = sq;
    __syncthreads();
    float var = 0.f;
    #pragma unroll
    for (int w2 = 0; w2 < 8; w2++) var += red[w2];
    float rstd = rsqrtf(var * (1.f / ND) + 1e-5f);

    #pragma unroll
    for (int k = 0; k < 4; k++) {
        int j = t + k*256;
        x[j] = (v[k] - mean) * rstd * w[j] + b[j];
    }
}

// ---------------- input stage: h1 = leaky(t*w1 + b1) ----------------
__global__ void k_build_h1(const float* __restrict__ target,
                           const float* __restrict__ bos,
                           const float* __restrict__ w1,
                           const float* __restrict__ b1,
                           float* __restrict__ h1)
{
    int idx = blockIdx.x * blockDim.x + threadIdx.x;   // NB*NS*NHID
    int j = idx % NHID;
    int bs = idx / NHID;
    int s = bs % NS, bb = bs / NS;
    float t = (s == 0) ? bos[0] : target[bb*NL + s - 1];
    float v = t * w1[j] + b1[j];
    h1[idx] = (v >= 0.f) ? v : 0.01f * v;
}

// ---------------- fill tgt (+PE, +prev/cur) and mem ----------------
__global__ void k_fill(const float* __restrict__ gs,
                       const float* __restrict__ prev,
                       const float* __restrict__ cur,
                       float* __restrict__ h, float* __restrict__ mem)
{
    int idx = blockIdx.x * blockDim.x + threadIdx.x;   // NB*NS*ND
    int j = idx % ND;
    int bs = idx / ND;
    int s = bs % NS, bb = bs / NS;
    float hv, mv;
    if (j < NHID) {
        int jj = j & ~1;
        float div = expf(-logf(10000.f) * (float)jj / (float)NHID);
        float ang = (float)s * div;
        float pe = (j & 1) ? cosf(ang) : sinf(ang);
        hv = h[idx] + pe;
        mv = gs[(long long)bs * NHID + j];
    } else if (j < NHID + NEA) {
        float p = prev[bb*NEA + (j - NHID)];
        hv = p; mv = p;
    } else {
        float c = cur[bb*NEA + (j - NHID - NEA)];
        hv = c; mv = c;
    }
    h[idx] = hv;
    mem[idx] = mv;
}

// ---------------- output head: dot with proj_w2, mask ----------------
__global__ void k_final(const float* __restrict__ p1,
                        const float* __restrict__ w2,
                        const float* __restrict__ b2,
                        const int* __restrict__ basis,
                        float* __restrict__ out)
{
    int warp = (blockIdx.x * blockDim.x + threadIdx.x) >> 5;
    int lane = threadIdx.x & 31;
    if (warp >= NB * NL) return;
    int bb = warp / NL, l = warp % NL;
    const float* rowp = p1 + ((long long)bb * NS + l + 1) * NHID;
    float sum = 0.f;
    #pragma unroll 4
    for (int j = lane; j < NHID; j += 32) sum += rowp[j] * w2[j];
    #pragma unroll
    for (int off = 16; off; off >>= 1) sum += __shfl_xor_sync(0xFFFFFFFFu, sum, off);
    if (lane == 0)
        out[warp] = (l < basis[bb]) ? (sum + b2[0]) : 0.f;
}

// ---------------- host side ----------------
static void gemm_tn(const float* A, int lda, const float* W, int ldb,
                    float* C, int ldc, const float* bias, const float* resid,
                    int M, int N, int K, float alpha, int act)
{
    dim3 g(N / 128, M / 128, 1);
    k_gemm<true><<<g, 256>>>(A, lda, 0, 0, W, ldb, 0, 0, C, ldc, 0, 0,
                             bias, resid, M, N, K, 1, alpha, act, 0);
}

extern "C" void kernel_launch(void* const* d_in, const int* in_sizes, int n_in,
                              void* d_out, int out_size)
{
    const float* gs      = (const float*)d_in[0];
    const float* prev    = (const float*)d_in[1];
    const float* cur     = (const float*)d_in[2];
    const float* target  = (const float*)d_in[3];
    const float* bos     = (const float*)d_in[4];
    const float* inp_w1  = (const float*)d_in[5];
    const float* inp_b1  = (const float*)d_in[6];
    const float* inp_w2  = (const float*)d_in[7];
    const float* inp_b2  = (const float*)d_in[8];
    const float* sa_qkv_w = (const float*)d_in[9];
    const float* sa_qkv_b = (const float*)d_in[10];
    const float* sa_out_w = (const float*)d_in[11];
    const float* sa_out_b = (const float*)d_in[12];
    const float* ca_qkv_w = (const float*)d_in[13];
    const float* ca_qkv_b = (const float*)d_in[14];
    const float* ca_out_w = (const float*)d_in[15];
    const float* ca_out_b = (const float*)d_in[16];
    const float* ln_w    = (const float*)d_in[17];
    const float* ln_b    = (const float*)d_in[18];
    const float* ff_w1   = (const float*)d_in[19];
    const float* ff_b1   = (const float*)d_in[20];
    const float* ff_w2   = (const float*)d_in[21];
    const float* ff_b2   = (const float*)d_in[22];
    const float* proj_w1 = (const float*)d_in[23];
    const float* proj_b1 = (const float*)d_in[24];
    const float* proj_w2 = (const float*)d_in[25];
    const float* proj_b2 = (const float*)d_in[26];
    const int*   basis   = (const int*)d_in[27];
    float* out = (float*)d_out;

    float *h_, *mem_, *qkv_, *att_, *ao_, *ff_, *p1_;
    cudaGetSymbolAddress((void**)&h_,   g_h);
    cudaGetSymbolAddress((void**)&mem_, g_mem);
    cudaGetSymbolAddress((void**)&qkv_, g_qkv);
    cudaGetSymbolAddress((void**)&att_, g_att);
    cudaGetSymbolAddress((void**)&ao_,  g_ao);
    cudaGetSymbolAddress((void**)&ff_,  g_ff);
    cudaGetSymbolAddress((void**)&p1_,  g_p1);

    const int M = NB * NS;         // 8192 tokens
    const float isq = 1.f / 16.f;  // 1/sqrt(256)

    // ---- input stage ----
    k_build_h1<<<(NB*NS*NHID)/256, 256>>>(target, bos, inp_w1, inp_b1, p1_);
    gemm_tn(p1_, NHID, inp_w2, NHID, h_, ND, inp_b2, nullptr, M, NHID, NHID, 1.f, 0);
    k_fill<<<(NB*NS*ND)/256, 256>>>(gs, prev, cur, h_, mem_);

    for (int l = 0; l < 3; l++) {
        const float* qkvw = sa_qkv_w + (long long)l * 3*ND*ND;
        const float* qkvb = sa_qkv_b + l * 3*ND;
        const float* ow   = sa_out_w + (long long)l * ND*ND;
        const float* ob   = sa_out_b + l * ND;

        // ===== self-attention (causal) =====
        gemm_tn(h_, ND, qkvw, ND, qkv_, 3*ND, qkvb, nullptr, M, 3*ND, ND, 1.f, 0);
        {
            dim3 g(NS/128, NS/128, NB*NNH);
            k_gemm<true><<<g, 256>>>(qkv_, 3*ND, (long long)NS*3*ND, NHD,
                                     qkv_ + ND, 3*ND, (long long)NS*3*ND, NHD,
                                     att_, NS, (long long)NNH*NS*NS, (long long)NS*NS,
                                     nullptr, nullptr, NS, NS, NHD, NNH, isq, 0, 1);
        }
        k_softmax<<<NB*NNH*NS, 256>>>(att_, 1);
        {
            dim3 g(NHD/128, NS/128, NB*NNH);
            k_gemm<false><<<g, 256>>>(att_, NS, (long long)NNH*NS*NS, (long long)NS*NS,
                                      qkv_ + 2*ND, 3*ND, (long long)NS*3*ND, NHD,
                                      ao_, ND, (long long)NS*ND, NHD,
                                      nullptr, nullptr, NS, NHD, NS, NNH, 1.f, 0, 0);
        }
        gemm_tn(ao_, ND, ow, ND, h_, ND, ob, h_, M, ND, ND, 1.f, 0);
        k_ln<<<M, 256>>>(h_, ln_w + (l*3 + 0)*ND, ln_b + (l*3 + 0)*ND);

        // ===== cross-attention =====
        qkvw = ca_qkv_w + (long long)l * 3*ND*ND;
        qkvb = ca_qkv_b + l * 3*ND;
        ow   = ca_out_w + (long long)l * ND*ND;
        ob   = ca_out_b + l * ND;
        gemm_tn(h_,   ND, qkvw,           ND, qkv_,      3*ND, qkvb,      nullptr, M,   ND, ND, 1.f, 0);
        gemm_tn(mem_, ND, qkvw + ND*ND,   ND, qkv_ + ND, 3*ND, qkvb + ND, nullptr, M, 2*ND, ND, 1.f, 0);
        {
            dim3 g(NS/128, NS/128, NB*NNH);
            k_gemm<true><<<g, 256>>>(qkv_, 3*ND, (long long)NS*3*ND, NHD,
                                     qkv_ + ND, 3*ND, (long long)NS*3*ND, NHD,
                                     att_, NS, (long long)NNH*NS*NS, (long long)NS*NS,
                                     nullptr, nullptr, NS, NS, NHD, NNH, isq, 0, 0);
        }
        k_softmax<<<NB*NNH*NS, 256>>>(att_, 0);
        {
            dim3 g(NHD/128, NS/128, NB*NNH);
            k_gemm<false><<<g, 256>>>(att_, NS, (long long)NNH*NS*NS, (long long)NS*NS,
                                      qkv_ + 2*ND, 3*ND, (long long)NS*3*ND, NHD,
                                      ao_, ND, (long long)NS*ND, NHD,
                                      nullptr, nullptr, NS, NHD, NS, NNH, 1.f, 0, 0);
        }
        gemm_tn(ao_, ND, ow, ND, h_, ND, ob, h_, M, ND, ND, 1.f, 0);
        k_ln<<<M, 256>>>(h_, ln_w + (l*3 + 1)*ND, ln_b + (l*3 + 1)*ND);

        // ===== feed-forward =====
        gemm_tn(h_, ND, ff_w1 + (long long)l*NDFF*ND, ND, ff_, NDFF,
                ff_b1 + l*NDFF, nullptr, M, NDFF, ND, 1.f, 1);
        gemm_tn(ff_, NDFF, ff_w2 + (long long)l*ND*NDFF, NDFF, h_, ND,
                ff_b2 + l*ND, h_, M, ND, NDFF, 1.f, 0);
        k_ln<<<M, 256>>>(h_, ln_w + (l*3 + 2)*ND, ln_b + (l*3 + 2)*ND);
    }

    // ---- output head ----
    gemm_tn(h_, ND, proj_w1, ND, p1_, NHID, proj_b1, nullptr, M, NHID, ND, 1.f, 2);
    k_final<<<(NB*NL*32 + 255)/256, 256>>>(p1_, proj_w2, proj_b2, basis, out);
}

// round 8
// speedup vs baseline: 3.1820x; 1.1106x over previous
#include <cuda_runtime.h>
#include <cuda_bf16.h>
#include <math.h>
#include <stdint.h>

// Problem constants
#define NB   16
#define NL   511
#define NS   512
#define ND   1024
#define NHID 512
#define NDFF 2048
#define NEA  256
#define NNH  4
#define NHD  256   // head dim

// ---------------- device scratch ----------------
__device__ float g_h  [NB*NS*ND];      // residual stream (fp32)
__device__ float g_att[NB*NNH*NS*NS];  // attention scores (fp32, pre-softmax)
__device__ float g_p1 [NB*NS*NHID];

// split bf16 planes (hi / lo)
__device__ __nv_bfloat16 g_hH [NB*NS*ND],    g_hL [NB*NS*ND];
__device__ __nv_bfloat16 g_memH[NB*NS*ND],   g_memL[NB*NS*ND];
__device__ __nv_bfloat16 g_qkvH[NB*NS*3*ND], g_qkvL[NB*NS*3*ND];
__device__ __nv_bfloat16 g_attH[NB*NNH*NS*NS], g_attL[NB*NNH*NS*NS];
__device__ __nv_bfloat16 g_ffH[NB*NS*NDFF],  g_ffL[NB*NS*NDFF];
__device__ __nv_bfloat16 g_aoH[NB*NS*ND],    g_aoL[NB*NS*ND];
__device__ __nv_bfloat16 g_h1H[NB*NS*NHID],  g_h1L[NB*NS*NHID];

// weight planes (converted once per launch)
#define OFF_SAQKV  0LL
#define OFF_CAQKV  9437184LL
#define OFF_SAOUT  18874368LL
#define OFF_CAOUT  22020096LL
#define OFF_FF1    25165824LL
#define OFF_FF2    31457280LL
#define OFF_INPW2  37748736LL
#define OFF_PROJ1  38010880LL
#define W_TOTAL    38535168LL
__device__ __nv_bfloat16 g_wH[W_TOTAL], g_wL[W_TOTAL];

// ---------------- helpers ----------------
static __device__ __forceinline__ void split_pack2(float x0, float x1,
                                                   uint32_t &h, uint32_t &l)
{
    __nv_bfloat16 h0 = __float2bfloat16_rn(x0);
    __nv_bfloat16 h1 = __float2bfloat16_rn(x1);
    __nv_bfloat16 l0 = __float2bfloat16_rn(x0 - __bfloat162float(h0));
    __nv_bfloat16 l1 = __float2bfloat16_rn(x1 - __bfloat162float(h1));
    h = ((uint32_t)__bfloat16_as_ushort(h1) << 16) | (uint32_t)__bfloat16_as_ushort(h0);
    l = ((uint32_t)__bfloat16_as_ushort(l1) << 16) | (uint32_t)__bfloat16_as_ushort(l0);
}

static __device__ __forceinline__ void mma_bf16(float c[4],
    const uint32_t a[4], const uint32_t b[2])
{
    asm volatile(
        "mma.sync.aligned.m16n8k16.row.col.f32.bf16.bf16.f32 "
        "{%0,%1,%2,%3},{%4,%5,%6,%7},{%8,%9},{%0,%1,%2,%3};"
        : "+f"(c[0]), "+f"(c[1]), "+f"(c[2]), "+f"(c[3])
        : "r"(a[0]), "r"(a[1]), "r"(a[2]), "r"(a[3]), "r"(b[0]), "r"(b[1]));
}

static __device__ __forceinline__ void ldsm4(uint32_t &r0, uint32_t &r1,
                                             uint32_t &r2, uint32_t &r3, uint32_t a)
{
    asm volatile("ldmatrix.sync.aligned.m8n8.x4.shared.b16 {%0,%1,%2,%3},[%4];"
        : "=r"(r0), "=r"(r1), "=r"(r2), "=r"(r3) : "r"(a));
}

static __device__ __forceinline__ void ldsm4t(uint32_t &r0, uint32_t &r1,
                                              uint32_t &r2, uint32_t &r3, uint32_t a)
{
    asm volatile("ldmatrix.sync.aligned.m8n8.x4.trans.shared.b16 {%0,%1,%2,%3},[%4];"
        : "=r"(r0), "=r"(r1), "=r"(r2), "=r"(r3) : "r"(a));
}

static __device__ __forceinline__ void cp16(uint32_t dst, const void* src)
{
    asm volatile("cp.async.cg.shared.global [%0], [%1], 16;" :: "r"(dst), "l"(src));
}
static __device__ __forceinline__ void cp_commit()
{
    asm volatile("cp.async.commit_group;");
}
template<int N> static __device__ __forceinline__ void cp_wait()
{
    asm volatile("cp.async.wait_group %0;" :: "n"(N));
}

// swizzled byte offset within a [128 rows x 16 elems] bf16 stage (32B rows, 2x16B chunks)
static __device__ __forceinline__ uint32_t swz(int row, int ch)
{
    return (uint32_t)(row * 32 + ((ch ^ ((row >> 2) & 1)) << 4));
}

// ---------------- tensor-core tiled GEMM (bf16x3 emulated fp32) -------------
// C = act(alpha * A @ op(B) + bias) [+ resid]  and/or split-bf16 planes CH/CL.
// A,B given as pre-split bf16 hi/lo planes. Tile 128x128, kstep 16, 2-stage
// cp.async pipeline, 8 warps (4M x 2N), warp tile 32x64, mma m16n8k16.
// TRANSB=true : op(B)=B^T, B is [N,K] row-major.  TRANSB=false: B is [K,N].
template<bool TRANSB>
__global__ __launch_bounds__(256) void k_gemm(
    const __nv_bfloat16* __restrict__ AH, const __nv_bfloat16* __restrict__ AL,
    int lda, long long strAb, long long strAh,
    const __nv_bfloat16* __restrict__ BH, const __nv_bfloat16* __restrict__ BL,
    int ldb, long long strBb, long long strBh,
    float* __restrict__ C, __nv_bfloat16* __restrict__ CH, __nv_bfloat16* __restrict__ CL,
    int ldc, long long strCb, long long strCh,
    const float* __restrict__ bias, const float* __restrict__ resid,
    int K, int nh, float alpha, int act, int causal)
{
    int z = blockIdx.z;
    int zb = z / nh, zh = z % nh;
    AH += zb*strAb + zh*strAh;  AL += zb*strAb + zh*strAh;
    BH += zb*strBb + zh*strBh;  BL += zb*strBb + zh*strBh;
    long long coff = zb*strCb + zh*strCh;
    if (C)  C  += coff;
    if (CH) { CH += coff; CL += coff; }

    int m0 = blockIdx.y * 128, n0 = blockIdx.x * 128;
    if (causal && n0 > m0) return;   // fully-masked tile

    __shared__ __nv_bfloat16 sAH[2*128*16], sAL[2*128*16];
    constexpr int BSTGE = TRANSB ? 128*16 : 16*136;
    __shared__ __nv_bfloat16 sBH[2*BSTGE], sBL[2*BSTGE];
    constexpr uint32_t ASTG = 128*16*2;     // stage stride bytes
    constexpr uint32_t BSTG = BSTGE*2;

    int tid  = threadIdx.x;
    int lane = tid & 31;
    int wid  = tid >> 5;
    int wm = (wid & 3) * 32;
    int wn = (wid >> 2) * 64;
    int qr = lane >> 2;
    int qc = lane & 3;

    // loader indices
    int arow = tid >> 1;            // 0..127
    int ach  = tid & 1;             // 16B chunk (k 0-7 / 8-15)
    int bkr  = tid >> 4;            // 0..15   (non-T: k row)
    int bch  = tid & 15;            // 0..15   (non-T: 16B chunk along n)

    uint32_t baseAH = (uint32_t)__cvta_generic_to_shared(sAH);
    uint32_t baseAL = (uint32_t)__cvta_generic_to_shared(sAL);
    uint32_t baseBH = (uint32_t)__cvta_generic_to_shared(sBH);
    uint32_t baseBL = (uint32_t)__cvta_generic_to_shared(sBL);

    uint32_t dA = swz(arow, ach);
    uint32_t dB = TRANSB ? swz(arow, ach) : (uint32_t)((bkr*136 + bch*8) * 2);

    // running global pointers
    const __nv_bfloat16 *pAH = AH + (long long)(m0 + arow)*lda + ach*8;
    const __nv_bfloat16 *pAL = AL + (long long)(m0 + arow)*lda + ach*8;
    const __nv_bfloat16 *pBH, *pBL;
    if (TRANSB) {
        pBH = BH + (long long)(n0 + arow)*ldb + ach*8;
        pBL = BL + (long long)(n0 + arow)*ldb + ach*8;
    } else {
        pBH = BH + (long long)bkr*ldb + n0 + bch*8;
        pBL = BL + (long long)bkr*ldb + n0 + bch*8;
    }

    // fragment read offsets (loop-invariant)
    uint32_t aoff[2];
    #pragma unroll
    for (int mt = 0; mt < 2; mt++)
        aoff[mt] = swz(wm + mt*16 + (lane & 15), lane >> 4);

    uint32_t boff[4];
    #pragma unroll
    for (int p = 0; p < 4; p++) {
        if (TRANSB) {
            int rr = wn + p*16 + ((lane >> 4) << 3) + (lane & 7);
            boff[p] = swz(rr, (lane >> 3) & 1);
        } else {
            int rk = (((lane >> 3) & 1) << 3) + (lane & 7);
            int cn = wn + p*16 + ((lane >> 4) << 3);
            boff[p] = (uint32_t)((rk * 136 + cn) * 2);
        }
    }

    float c[2][8][4];
    #pragma unroll
    for (int i = 0; i < 2; i++)
        #pragma unroll
        for (int j = 0; j < 8; j++)
            #pragma unroll
            for (int t = 0; t < 4; t++) c[i][j][t] = 0.f;

    int itc = K >> 4;

    // prologue: stage 0
    cp16(baseAH + dA, pAH);  cp16(baseAL + dA, pAL);
    cp16(baseBH + dB, pBH);  cp16(baseBL + dB, pBL);
    cp_commit();
    pAH += 16; pAL += 16;
    if (TRANSB) { pBH += 16; pBL += 16; }
    else        { pBH += (long long)16*ldb; pBL += (long long)16*ldb; }

    for (int it = 0; it < itc; it++) {
        uint32_t buf = (uint32_t)(it & 1);
        if (it + 1 < itc) {
            uint32_t nb = (uint32_t)((it + 1) & 1);
            cp16(baseAH + nb*ASTG + dA, pAH);
            cp16(baseAL + nb*ASTG + dA, pAL);
            cp16(baseBH + nb*BSTG + dB, pBH);
            cp16(baseBL + nb*BSTG + dB, pBL);
            cp_commit();
            pAH += 16; pAL += 16;
            if (TRANSB) { pBH += 16; pBL += 16; }
            else        { pBH += (long long)16*ldb; pBL += (long long)16*ldb; }
            cp_wait<1>();
        } else {
            cp_wait<0>();
        }
        __syncthreads();

        uint32_t aH[2][4], aL[2][4];
        #pragma unroll
        for (int mt = 0; mt < 2; mt++) {
            ldsm4(aH[mt][0], aH[mt][1], aH[mt][2], aH[mt][3], baseAH + buf*ASTG + aoff[mt]);
            ldsm4(aL[mt][0], aL[mt][1], aL[mt][2], aL[mt][3], baseAL + buf*ASTG + aoff[mt]);
        }
        uint32_t bH[8][2], bL[8][2];
        #pragma unroll
        for (int p = 0; p < 4; p++) {
            uint32_t r0, r1, r2, r3;
            if (TRANSB) ldsm4 (r0, r1, r2, r3, baseBH + buf*BSTG + boff[p]);
            else        ldsm4t(r0, r1, r2, r3, baseBH + buf*BSTG + boff[p]);
            bH[2*p][0] = r0; bH[2*p][1] = r1; bH[2*p+1][0] = r2; bH[2*p+1][1] = r3;
            if (TRANSB) ldsm4 (r0, r1, r2, r3, baseBL + buf*BSTG + boff[p]);
            else        ldsm4t(r0, r1, r2, r3, baseBL + buf*BSTG + boff[p]);
            bL[2*p][0] = r0; bL[2*p][1] = r1; bL[2*p+1][0] = r2; bL[2*p+1][1] = r3;
        }

        #pragma unroll
        for (int mt = 0; mt < 2; mt++) {
            #pragma unroll
            for (int nt = 0; nt < 8; nt++) {
                mma_bf16(c[mt][nt], aH[mt], bH[nt]);
                mma_bf16(c[mt][nt], aH[mt], bL[nt]);
                mma_bf16(c[mt][nt], aL[mt], bH[nt]);
            }
        }
        __syncthreads();
    }

    // ---- epilogue ----
    #pragma unroll
    for (int mt = 0; mt < 2; mt++) {
        #pragma unroll
        for (int half = 0; half < 2; half++) {
            long long row = m0 + wm + mt*16 + qr + half*8;
            #pragma unroll
            for (int nt = 0; nt < 8; nt++) {
                int col = n0 + wn + nt*8 + 2*qc;
                float v0 = c[mt][nt][half*2+0] * alpha;
                float v1 = c[mt][nt][half*2+1] * alpha;
                if (bias) { v0 += bias[col]; v1 += bias[col+1]; }
                if (act == 1) { v0 = fmaxf(v0, 0.f); v1 = fmaxf(v1, 0.f); }
                else if (act == 2) {
                    v0 = (v0 >= 0.f) ? v0 : 0.01f * v0;
                    v1 = (v1 >= 0.f) ? v1 : 0.01f * v1;
                }
                if (resid) {
                    float2 rv = *(const float2*)(resid + row*ldc + col);
                    v0 += rv.x; v1 += rv.y;
                }
                if (C) *(float2*)(C + row*ldc + col) = make_float2(v0, v1);
                if (CH) {
                    uint32_t hp, lp;
                    split_pack2(v0, v1, hp, lp);
                    *(uint32_t*)(CH + row*ldc + col) = hp;
                    *(uint32_t*)(CL + row*ldc + col) = lp;
                }
            }
        }
    }
}

// ---------------- split convert: fp32 -> hi/lo bf16 planes ----------------
__global__ void k_split(const float4* __restrict__ src,
                        uint2* __restrict__ dH, uint2* __restrict__ dL, int n4)
{
    int i = blockIdx.x * blockDim.x + threadIdx.x;
    if (i >= n4) return;
    float4 v = src[i];
    uint2 H, L;
    split_pack2(v.x, v.y, H.x, L.x);
    split_pack2(v.z, v.w, H.y, L.y);
    dH[i] = H;
    dL[i] = L;
}

// ---------------- softmax over rows of S=512 (writes split planes) --------
__global__ __launch_bounds__(256) void k_softmax(const float* __restrict__ att,
                                                 __nv_bfloat16* __restrict__ oH,
                                                 __nv_bfloat16* __restrict__ oL,
                                                 int causal)
{
    int gid = blockIdx.x;
    int i = gid & (NS - 1);
    const float* row = att + (long long)gid * NS;
    int len = causal ? (i + 1) : NS;
    int t = threadIdx.x;

    float v0 = (t       < len) ? row[t]       : -1e30f;
    float v1 = (t + 256 < len) ? row[t + 256] : -1e30f;

    __shared__ float red[8];
    float m = fmaxf(v0, v1);
    #pragma unroll
    for (int off = 16; off; off >>= 1) m = fmaxf(m, __shfl_xor_sync(0xFFFFFFFFu, m, off));
    if ((t & 31) == 0) red[t >> 5] = m;
    __syncthreads();
    float mm = red[0];
    #pragma unroll
    for (int w = 1; w < 8; w++) mm = fmaxf(mm, red[w]);
    __syncthreads();

    float e0 = (t       < len) ? __expf(v0 - mm) : 0.f;
    float e1 = (t + 256 < len) ? __expf(v1 - mm) : 0.f;
    float s = e0 + e1;
    #pragma unroll
    for (int off = 16; off; off >>= 1) s += __shfl_xor_sync(0xFFFFFFFFu, s, off);
    if ((t & 31) == 0) red[t >> 5] = s;
    __syncthreads();
    float ss = 0.f;
    #pragma unroll
    for (int w = 0; w < 8; w++) ss += red[w];
    float inv = 1.f / ss;
    e0 *= inv; e1 *= inv;

    long long base = (long long)gid * NS;
    __nv_bfloat16 h0 = __float2bfloat16_rn(e0);
    __nv_bfloat16 h1 = __float2bfloat16_rn(e1);
    oH[base + t]       = h0;
    oH[base + t + 256] = h1;
    oL[base + t]       = __float2bfloat16_rn(e0 - __bfloat162float(h0));
    oL[base + t + 256] = __float2bfloat16_rn(e1 - __bfloat162float(h1));
}

// ---------------- LayerNorm over D=1024 (in place + split planes) ---------
__global__ __launch_bounds__(256) void k_ln(float* __restrict__ h,
                                            const float* __restrict__ w,
                                            const float* __restrict__ b,
                                            __nv_bfloat16* __restrict__ oH,
                                            __nv_bfloat16* __restrict__ oL)
{
    long long base = (long long)blockIdx.x * ND;
    float* x = h + base;
    int t = threadIdx.x;
    float v[4];
    float s = 0.f;
    #pragma unroll
    for (int k = 0; k < 4; k++) { v[k] = x[t + k*256]; s += v[k]; }

    __shared__ float red[8];
    #pragma unroll
    for (int off = 16; off; off >>= 1) s += __shfl_xor_sync(0xFFFFFFFFu, s, off);
    if ((t & 31) == 0) red[t >> 5] = s;
    __syncthreads();
    float sum = 0.f;
    #pragma unroll
    for (int w2 = 0; w2 < 8; w2++) sum += red[w2];
    float mean = sum * (1.f / ND);
    __syncthreads();

    float sq = 0.f;
    #pragma unroll
    for (int k = 0; k < 4; k++) { float d = v[k] - mean; sq += d*d; }
    #pragma unroll
    for (int off = 16; off; off >>= 1) sq += __shfl_xor_sync(0xFFFFFFFFu, sq, off);
    if ((t & 31) == 0) red[t >> 5] = sq;
    __syncthreads();
    float var = 0.f;
    #pragma unroll
    for (int w2 = 0; w2 < 8; w2++) var += red[w2];
    float rstd = rsqrtf(var * (1.f / ND) + 1e-5f);

    #pragma unroll
    for (int k = 0; k < 4; k++) {
        int j = t + k*256;
        float y = (v[k] - mean) * rstd * w[j] + b[j];
        x[j] = y;
        __nv_bfloat16 hh = __float2bfloat16_rn(y);
        oH[base + j] = hh;
        oL[base + j] = __float2bfloat16_rn(y - __bfloat162float(hh));
    }
}

// ---------------- input stage: h1 = leaky(t*w1 + b1) -> split planes ------
__global__ void k_build_h1(const float* __restrict__ target,
                           const float* __restrict__ bos,
                           const float* __restrict__ w1,
                           const float* __restrict__ b1,
                           __nv_bfloat16* __restrict__ oH,
                           __nv_bfloat16* __restrict__ oL)
{
    int idx = blockIdx.x * blockDim.x + threadIdx.x;   // NB*NS*NHID
    int j = idx % NHID;
    int bs = idx / NHID;
    int s = bs % NS, bb = bs / NS;
    float t = (s == 0) ? bos[0] : target[bb*NL + s - 1];
    float v = t * w1[j] + b1[j];
    v = (v >= 0.f) ? v : 0.01f * v;
    __nv_bfloat16 hh = __float2bfloat16_rn(v);
    oH[idx] = hh;
    oL[idx] = __float2bfloat16_rn(v - __bfloat162float(hh));
}

// ---------------- fill tgt (+PE, +prev/cur) and mem ----------------
__global__ void k_fill(const float* __restrict__ gs,
                       const float* __restrict__ prev,
                       const float* __restrict__ cur,
                       float* __restrict__ h,
                       __nv_bfloat16* __restrict__ hH, __nv_bfloat16* __restrict__ hL,
                       __nv_bfloat16* __restrict__ mH, __nv_bfloat16* __restrict__ mL)
{
    int idx = blockIdx.x * blockDim.x + threadIdx.x;   // NB*NS*ND
    int j = idx % ND;
    int bs = idx / ND;
    int s = bs % NS, bb = bs / NS;
    float hv, mv;
    if (j < NHID) {
        int jj = j & ~1;
        float div = expf(-logf(10000.f) * (float)jj / (float)NHID);
        float ang = (float)s * div;
        float pe = (j & 1) ? cosf(ang) : sinf(ang);
        hv = h[idx] + pe;
        mv = gs[(long long)bs * NHID + j];
    } else if (j < NHID + NEA) {
        float p = prev[bb*NEA + (j - NHID)];
        hv = p; mv = p;
    } else {
        float c = cur[bb*NEA + (j - NHID - NEA)];
        hv = c; mv = c;
    }
    h[idx] = hv;
    __nv_bfloat16 hh = __float2bfloat16_rn(hv);
    hH[idx] = hh;
    hL[idx] = __float2bfloat16_rn(hv - __bfloat162float(hh));
    __nv_bfloat16 mh = __float2bfloat16_rn(mv);
    mH[idx] = mh;
    mL[idx] = __float2bfloat16_rn(mv - __bfloat162float(mh));
}

// ---------------- output head: dot with proj_w2, mask ----------------
__global__ void k_final(const float* __restrict__ p1,
                        const float* __restrict__ w2,
                        const float* __restrict__ b2,
                        const int* __restrict__ basis,
                        float* __restrict__ out)
{
    int warp = (blockIdx.x * blockDim.x + threadIdx.x) >> 5;
    int lane = threadIdx.x & 31;
    if (warp >= NB * NL) return;
    int bb = warp / NL, l = warp % NL;
    const float* rowp = p1 + ((long long)bb * NS + l + 1) * NHID;
    float sum = 0.f;
    #pragma unroll 4
    for (int j = lane; j < NHID; j += 32) sum += rowp[j] * w2[j];
    #pragma unroll
    for (int off = 16; off; off >>= 1) sum += __shfl_xor_sync(0xFFFFFFFFu, sum, off);
    if (lane == 0)
        out[warp] = (l < basis[bb]) ? (sum + b2[0]) : 0.f;
}

// ---------------- host side ----------------
static void split_w(const float* src, __nv_bfloat16* wH, __nv_bfloat16* wL,
                    long long off, long long n)
{
    int n4 = (int)(n >> 2);
    k_split<<<(n4 + 255)/256, 256>>>((const float4*)src,
                                     (uint2*)(wH + off), (uint2*)(wL + off), n4);
}

extern "C" void kernel_launch(void* const* d_in, const int* in_sizes, int n_in,
                              void* d_out, int out_size)
{
    const float* gs      = (const float*)d_in[0];
    const float* prev    = (const float*)d_in[1];
    const float* cur     = (const float*)d_in[2];
    const float* target  = (const float*)d_in[3];
    const float* bos     = (const float*)d_in[4];
    const float* inp_w1  = (const float*)d_in[5];
    const float* inp_b1  = (const float*)d_in[6];
    const float* inp_w2  = (const float*)d_in[7];
    const float* inp_b2  = (const float*)d_in[8];
    const float* sa_qkv_w = (const float*)d_in[9];
    const float* sa_qkv_b = (const float*)d_in[10];
    const float* sa_out_w = (const float*)d_in[11];
    const float* sa_out_b = (const float*)d_in[12];
    const float* ca_qkv_w = (const float*)d_in[13];
    const float* ca_qkv_b = (const float*)d_in[14];
    const float* ca_out_w = (const float*)d_in[15];
    const float* ca_out_b = (const float*)d_in[16];
    const float* ln_w    = (const float*)d_in[17];
    const float* ln_b    = (const float*)d_in[18];
    const float* ff_w1   = (const float*)d_in[19];
    const float* ff_b1   = (const float*)d_in[20];
    const float* ff_w2   = (const float*)d_in[21];
    const float* ff_b2   = (const float*)d_in[22];
    const float* proj_w1 = (const float*)d_in[23];
    const float* proj_b1 = (const float*)d_in[24];
    const float* proj_w2 = (const float*)d_in[25];
    const float* proj_b2 = (const float*)d_in[26];
    const int*   basis   = (const int*)d_in[27];
    float* out = (float*)d_out;

    float *h_, *att_, *p1_;
    __nv_bfloat16 *hH, *hL, *memH, *memL, *qkvH, *qkvL, *attH, *attL;
    __nv_bfloat16 *ffH, *ffL, *aoH, *aoL, *h1H, *h1L, *wH, *wL;
    cudaGetSymbolAddress((void**)&h_,   g_h);
    cudaGetSymbolAddress((void**)&att_, g_att);
    cudaGetSymbolAddress((void**)&p1_,  g_p1);
    cudaGetSymbolAddress((void**)&hH,   g_hH);   cudaGetSymbolAddress((void**)&hL,   g_hL);
    cudaGetSymbolAddress((void**)&memH, g_memH); cudaGetSymbolAddress((void**)&memL, g_memL);
    cudaGetSymbolAddress((void**)&qkvH, g_qkvH); cudaGetSymbolAddress((void**)&qkvL, g_qkvL);
    cudaGetSymbolAddress((void**)&attH, g_attH); cudaGetSymbolAddress((void**)&attL, g_attL);
    cudaGetSymbolAddress((void**)&ffH,  g_ffH);  cudaGetSymbolAddress((void**)&ffL,  g_ffL);
    cudaGetSymbolAddress((void**)&aoH,  g_aoH);  cudaGetSymbolAddress((void**)&aoL,  g_aoL);
    cudaGetSymbolAddress((void**)&h1H,  g_h1H);  cudaGetSymbolAddress((void**)&h1L,  g_h1L);
    cudaGetSymbolAddress((void**)&wH,   g_wH);   cudaGetSymbolAddress((void**)&wL,   g_wL);

    const int M = NB * NS;         // 8192 tokens
    const float isq = 1.f / 16.f;  // 1/sqrt(256)

    // ---- weight conversion (once per launch) ----
    split_w(sa_qkv_w, wH, wL, OFF_SAQKV, 3LL*3*ND*ND);
    split_w(ca_qkv_w, wH, wL, OFF_CAQKV, 3LL*3*ND*ND);
    split_w(sa_out_w, wH, wL, OFF_SAOUT, 3LL*ND*ND);
    split_w(ca_out_w, wH, wL, OFF_CAOUT, 3LL*ND*ND);
    split_w(ff_w1,    wH, wL, OFF_FF1,   3LL*NDFF*ND);
    split_w(ff_w2,    wH, wL, OFF_FF2,   3LL*ND*NDFF);
    split_w(inp_w2,   wH, wL, OFF_INPW2, (long long)NHID*NHID);
    split_w(proj_w1,  wH, wL, OFF_PROJ1, (long long)NHID*ND);

    // ---- input stage ----
    k_build_h1<<<(NB*NS*NHID)/256, 256>>>(target, bos, inp_w1, inp_b1, h1H, h1L);
    {
        dim3 g(NHID/128, M/128);
        k_gemm<true><<<g, 256>>>(h1H, h1L, NHID, 0, 0,
                                 wH + OFF_INPW2, wL + OFF_INPW2, NHID, 0, 0,
                                 h_, nullptr, nullptr, ND, 0, 0,
                                 inp_b2, nullptr, NHID, 1, 1.f, 0, 0);
    }
    k_fill<<<(NB*NS*ND)/256, 256>>>(gs, prev, cur, h_, hH, hL, memH, memL);

    for (int l = 0; l < 3; l++) {
        long long wq = OFF_SAQKV + (long long)l * 3*ND*ND;
        long long wo = OFF_SAOUT + (long long)l * ND*ND;
        const float* qkvb = sa_qkv_b + l * 3*ND;
        const float* ob   = sa_out_b + l * ND;

        // ===== self-attention (causal) =====
        {
            dim3 g(3*ND/128, M/128);
            k_gemm<true><<<g, 256>>>(hH, hL, ND, 0, 0,
                                     wH + wq, wL + wq, ND, 0, 0,
                                     nullptr, qkvH, qkvL, 3*ND, 0, 0,
                                     qkvb, nullptr, ND, 1, 1.f, 0, 0);
        }
        {
            dim3 g(NS/128, NS/128, NB*NNH);
            k_gemm<true><<<g, 256>>>(qkvH, qkvL, 3*ND, (long long)NS*3*ND, NHD,
                                     qkvH + ND, qkvL + ND, 3*ND, (long long)NS*3*ND, NHD,
                                     att_, nullptr, nullptr, NS, (long long)NNH*NS*NS, (long long)NS*NS,
                                     nullptr, nullptr, NHD, NNH, isq, 0, 1);
        }
        k_softmax<<<NB*NNH*NS, 256>>>(att_, attH, attL, 1);
        {
            dim3 g(NHD/128, NS/128, NB*NNH);
            k_gemm<false><<<g, 256>>>(attH, attL, NS, (long long)NNH*NS*NS, (long long)NS*NS,
                                      qkvH + 2*ND, qkvL + 2*ND, 3*ND, (long long)NS*3*ND, NHD,
                                      nullptr, aoH, aoL, ND, (long long)NS*ND, NHD,
                                      nullptr, nullptr, NS, NNH, 1.f, 0, 0);
        }
        {
            dim3 g(ND/128, M/128);
            k_gemm<true><<<g, 256>>>(aoH, aoL, ND, 0, 0,
                                     wH + wo, wL + wo, ND, 0, 0,
                                     h_, nullptr, nullptr, ND, 0, 0,
                                     ob, h_, ND, 1, 1.f, 0, 0);
        }
        k_ln<<<M, 256>>>(h_, ln_w + (l*3 + 0)*ND, ln_b + (l*3 + 0)*ND, hH, hL);

        // ===== cross-attention =====
        wq = OFF_CAQKV + (long long)l * 3*ND*ND;
        wo = OFF_CAOUT + (long long)l * ND*ND;
        qkvb = ca_qkv_b + l * 3*ND;
        ob   = ca_out_b + l * ND;
        {
            dim3 g(ND/128, M/128);
            k_gemm<true><<<g, 256>>>(hH, hL, ND, 0, 0,
                                     wH + wq, wL + wq, ND, 0, 0,
                                     nullptr, qkvH, qkvL, 3*ND, 0, 0,
                                     qkvb, nullptr, ND, 1, 1.f, 0, 0);
        }
        {
            dim3 g(2*ND/128, M/128);
            k_gemm<true><<<g, 256>>>(memH, memL, ND, 0, 0,
                                     wH + wq + (long long)ND*ND, wL + wq + (long long)ND*ND, ND, 0, 0,
                                     nullptr, qkvH + ND, qkvL + ND, 3*ND, 0, 0,
                                     qkvb + ND, nullptr, ND, 1, 1.f, 0, 0);
        }
        {
            dim3 g(NS/128, NS/128, NB*NNH);
            k_gemm<true><<<g, 256>>>(qkvH, qkvL, 3*ND, (long long)NS*3*ND, NHD,
                                     qkvH + ND, qkvL + ND, 3*ND, (long long)NS*3*ND, NHD,
                                     att_, nullptr, nullptr, NS, (long long)NNH*NS*NS, (long long)NS*NS,
                                     nullptr, nullptr, NHD, NNH, isq, 0, 0);
        }
        k_softmax<<<NB*NNH*NS, 256>>>(att_, attH, attL, 0);
        {
            dim3 g(NHD/128, NS/128, NB*NNH);
            k_gemm<false><<<g, 256>>>(attH, attL, NS, (long long)NNH*NS*NS, (long long)NS*NS,
                                      qkvH + 2*ND, qkvL + 2*ND, 3*ND, (long long)NS*3*ND, NHD,
                                      nullptr, aoH, aoL, ND, (long long)NS*ND, NHD,
                                      nullptr, nullptr, NS, NNH, 1.f, 0, 0);
        }
        {
            dim3 g(ND/128, M/128);
            k_gemm<true><<<g, 256>>>(aoH, aoL, ND, 0, 0,
                                     wH + wo, wL + wo, ND, 0, 0,
                                     h_, nullptr, nullptr, ND, 0, 0,
                                     ob, h_, ND, 1, 1.f, 0, 0);
        }
        k_ln<<<M, 256>>>(h_, ln_w + (l*3 + 1)*ND, ln_b + (l*3 + 1)*ND, hH, hL);

        // ===== feed-forward =====
        {
            dim3 g(NDFF/128, M/128);
            long long wf = OFF_FF1 + (long long)l*NDFF*ND;
            k_gemm<true><<<g, 256>>>(hH, hL, ND, 0, 0,
                                     wH + wf, wL + wf, ND, 0, 0,
                                     nullptr, ffH, ffL, NDFF, 0, 0,
                                     ff_b1 + l*NDFF, nullptr, ND, 1, 1.f, 1, 0);
        }
        {
            dim3 g(ND/128, M/128);
            long long wf = OFF_FF2 + (long long)l*ND*NDFF;
            k_gemm<true><<<g, 256>>>(ffH, ffL, NDFF, 0, 0,
                                     wH + wf, wL + wf, NDFF, 0, 0,
                                     h_, nullptr, nullptr, ND, 0, 0,
                                     ff_b2 + l*ND, h_, NDFF, 1, 1.f, 0, 0);
        }
        k_ln<<<M, 256>>>(h_, ln_w + (l*3 + 2)*ND, ln_b + (l*3 + 2)*ND, hH, hL);
    }

    // ---- output head ----
    {
        dim3 g(NHID/128, M/128);
        k_gemm<true><<<g, 256>>>(hH, hL, ND, 0, 0,
                                 wH + OFF_PROJ1, wL + OFF_PROJ1, ND, 0, 0,
                                 p1_, nullptr, nullptr, NHID, 0, 0,
                                 proj_b1, nullptr, ND, 1, 1.f, 2, 0);
    }
    k_final<<<(NB*NL*32 + 255)/256, 256>>>(p1_, proj_w2, proj_b2, basis, out);
}

// round 9
// speedup vs baseline: 4.3981x; 1.3822x over previous
#include <cuda_runtime.h>
#include <cuda_bf16.h>
#include <math.h>
#include <stdint.h>

// Problem constants
#define NB   16
#define NL   511
#define NS   512
#define ND   1024
#define NHID 512
#define NDFF 2048
#define NEA  256
#define NNH  4
#define NHD  256   // head dim

// ---------------- device scratch ----------------
__device__ float g_h  [NB*NS*ND];      // residual stream (fp32)
__device__ float g_att[NB*NNH*NS*NS];  // attention scores (fp32, pre-softmax)
__device__ float g_p1 [NB*NS*NHID];

// split bf16 planes (hi / lo)
__device__ __nv_bfloat16 g_hH [NB*NS*ND],    g_hL [NB*NS*ND];
__device__ __nv_bfloat16 g_memH[NB*NS*ND],   g_memL[NB*NS*ND];
__device__ __nv_bfloat16 g_qkvH[NB*NS*3*ND], g_qkvL[NB*NS*3*ND];
__device__ __nv_bfloat16 g_attH[NB*NNH*NS*NS], g_attL[NB*NNH*NS*NS];
__device__ __nv_bfloat16 g_ffH[NB*NS*NDFF],  g_ffL[NB*NS*NDFF];
__device__ __nv_bfloat16 g_aoH[NB*NS*ND],    g_aoL[NB*NS*ND];
__device__ __nv_bfloat16 g_h1H[NB*NS*NHID],  g_h1L[NB*NS*NHID];

// weight planes (converted once per launch)
#define OFF_SAQKV  0LL
#define OFF_CAQKV  9437184LL
#define OFF_SAOUT  18874368LL
#define OFF_CAOUT  22020096LL
#define OFF_FF1    25165824LL
#define OFF_FF2    31457280LL
#define OFF_INPW2  37748736LL
#define OFF_PROJ1  38010880LL
#define W_TOTAL    38535168LL
__device__ __nv_bfloat16 g_wH[W_TOTAL], g_wL[W_TOTAL];

// ---------------- helpers ----------------
static __device__ __forceinline__ void split_pack2(float x0, float x1,
                                                   uint32_t &h, uint32_t &l)
{
    __nv_bfloat16 h0 = __float2bfloat16_rn(x0);
    __nv_bfloat16 h1 = __float2bfloat16_rn(x1);
    __nv_bfloat16 l0 = __float2bfloat16_rn(x0 - __bfloat162float(h0));
    __nv_bfloat16 l1 = __float2bfloat16_rn(x1 - __bfloat162float(h1));
    h = ((uint32_t)__bfloat16_as_ushort(h1) << 16) | (uint32_t)__bfloat16_as_ushort(h0);
    l = ((uint32_t)__bfloat16_as_ushort(l1) << 16) | (uint32_t)__bfloat16_as_ushort(l0);
}

static __device__ __forceinline__ void mma_bf16(float c[4],
    const uint32_t a[4], const uint32_t b[2])
{
    asm volatile(
        "mma.sync.aligned.m16n8k16.row.col.f32.bf16.bf16.f32 "
        "{%0,%1,%2,%3},{%4,%5,%6,%7},{%8,%9},{%0,%1,%2,%3};"
        : "+f"(c[0]), "+f"(c[1]), "+f"(c[2]), "+f"(c[3])
        : "r"(a[0]), "r"(a[1]), "r"(a[2]), "r"(a[3]), "r"(b[0]), "r"(b[1]));
}

static __device__ __forceinline__ void ldsm4(uint32_t &r0, uint32_t &r1,
                                             uint32_t &r2, uint32_t &r3, uint32_t a)
{
    asm volatile("ldmatrix.sync.aligned.m8n8.x4.shared.b16 {%0,%1,%2,%3},[%4];"
        : "=r"(r0), "=r"(r1), "=r"(r2), "=r"(r3) : "r"(a));
}

static __device__ __forceinline__ void ldsm4t(uint32_t &r0, uint32_t &r1,
                                              uint32_t &r2, uint32_t &r3, uint32_t a)
{
    asm volatile("ldmatrix.sync.aligned.m8n8.x4.trans.shared.b16 {%0,%1,%2,%3},[%4];"
        : "=r"(r0), "=r"(r1), "=r"(r2), "=r"(r3) : "r"(a));
}

static __device__ __forceinline__ void cp16(uint32_t dst, const void* src)
{
    asm volatile("cp.async.cg.shared.global [%0], [%1], 16;" :: "r"(dst), "l"(src));
}
static __device__ __forceinline__ void cp_commit()
{
    asm volatile("cp.async.commit_group;");
}
template<int N> static __device__ __forceinline__ void cp_wait()
{
    asm volatile("cp.async.wait_group %0;" :: "n"(N));
}

// swizzled byte offset within a [128 rows x 16 elems] bf16 stage (32B rows, 2x16B chunks)
static __device__ __forceinline__ uint32_t swz(int row, int ch)
{
    return (uint32_t)(row * 32 + ((ch ^ ((row >> 2) & 1)) << 4));
}

// ---------------- tensor-core tiled GEMM (bf16x3 emulated fp32) -------------
// C = act(alpha * A @ op(B) + bias) [+ resid]  and/or split-bf16 planes CH/CL.
// A,B pre-split bf16 hi/lo planes. Tile 128x128, kstep 16, THREE-stage
// cp.async pipeline (ONE __syncthreads per iter), 8 warps (4M x 2N),
// warp tile 32x64, mma m16n8k16, 2 CTAs/SM.
// TRANSB=true : op(B)=B^T, B is [N,K] row-major.  TRANSB=false: B is [K,N].
template<bool TRANSB>
__global__ __launch_bounds__(256, 2) void k_gemm(
    const __nv_bfloat16* __restrict__ AH, const __nv_bfloat16* __restrict__ AL,
    int lda, long long strAb, long long strAh,
    const __nv_bfloat16* __restrict__ BH, const __nv_bfloat16* __restrict__ BL,
    int ldb, long long strBb, long long strBh,
    float* __restrict__ C, __nv_bfloat16* __restrict__ CH, __nv_bfloat16* __restrict__ CL,
    int ldc, long long strCb, long long strCh,
    const float* __restrict__ bias, const float* __restrict__ resid,
    int K, int nh, float alpha, int act, int causal)
{
    int z = blockIdx.z;
    int zb = z / nh, zh = z % nh;
    AH += zb*strAb + zh*strAh;  AL += zb*strAb + zh*strAh;
    BH += zb*strBb + zh*strBh;  BL += zb*strBb + zh*strBh;
    long long coff = zb*strCb + zh*strCh;
    if (C)  C  += coff;
    if (CH) { CH += coff; CL += coff; }

    int m0 = blockIdx.y * 128, n0 = blockIdx.x * 128;
    if (causal && n0 > m0) return;   // fully-masked tile

    extern __shared__ char sdyn[];
    constexpr uint32_t ASTG = 128*16*2;                       // bytes per A stage
    constexpr uint32_t BSTG = TRANSB ? 128*16*2 : 16*136*2;   // bytes per B stage
    uint32_t base   = (uint32_t)__cvta_generic_to_shared(sdyn);
    uint32_t baseAH = base;
    uint32_t baseAL = base + 3*ASTG;
    uint32_t baseBH = base + 6*ASTG;
    uint32_t baseBL = base + 6*ASTG + 3*BSTG;

    int tid  = threadIdx.x;
    int lane = tid & 31;
    int wid  = tid >> 5;
    int wm = (wid & 3) * 32;
    int wn = (wid >> 2) * 64;
    int qr = lane >> 2;
    int qc = lane & 3;

    // loader indices
    int arow = tid >> 1;            // 0..127
    int ach  = tid & 1;             // 16B chunk (k 0-7 / 8-15)
    int bkr  = tid >> 4;            // 0..15   (non-T: k row)
    int bch  = tid & 15;            // 0..15   (non-T: 16B chunk along n)

    uint32_t dA = swz(arow, ach);
    uint32_t dB = TRANSB ? swz(arow, ach) : (uint32_t)((bkr*136 + bch*8) * 2);

    // running global pointers
    const __nv_bfloat16 *pAH = AH + (long long)(m0 + arow)*lda + ach*8;
    const __nv_bfloat16 *pAL = AL + (long long)(m0 + arow)*lda + ach*8;
    const __nv_bfloat16 *pBH, *pBL;
    if (TRANSB) {
        pBH = BH + (long long)(n0 + arow)*ldb + ach*8;
        pBL = BL + (long long)(n0 + arow)*ldb + ach*8;
    } else {
        pBH = BH + (long long)bkr*ldb + n0 + bch*8;
        pBL = BL + (long long)bkr*ldb + n0 + bch*8;
    }
    long long bstep = TRANSB ? 16 : (long long)16*ldb;

    // fragment read offsets (loop-invariant)
    uint32_t aoff[2];
    #pragma unroll
    for (int mt = 0; mt < 2; mt++)
        aoff[mt] = swz(wm + mt*16 + (lane & 15), lane >> 4);

    uint32_t boff[4];
    #pragma unroll
    for (int p = 0; p < 4; p++) {
        if (TRANSB) {
            int rr = wn + p*16 + ((lane >> 4) << 3) + (lane & 7);
            boff[p] = swz(rr, (lane >> 3) & 1);
        } else {
            int rk = (((lane >> 3) & 1) << 3) + (lane & 7);
            int cn = wn + p*16 + ((lane >> 4) << 3);
            boff[p] = (uint32_t)((rk * 136 + cn) * 2);
        }
    }

    float c[2][8][4];
    #pragma unroll
    for (int i = 0; i < 2; i++)
        #pragma unroll
        for (int j = 0; j < 8; j++)
            #pragma unroll
            for (int t = 0; t < 4; t++) c[i][j][t] = 0.f;

    int itc = K >> 4;

    // prologue: issue stages 0 and 1
    #pragma unroll
    for (int s = 0; s < 2; s++) {
        cp16(baseAH + s*ASTG + dA, pAH);
        cp16(baseAL + s*ASTG + dA, pAL);
        cp16(baseBH + s*BSTG + dB, pBH);
        cp16(baseBL + s*BSTG + dB, pBL);
        cp_commit();
        pAH += 16; pAL += 16; pBH += bstep; pBL += bstep;
    }

    for (int it = 0; it < itc; it++) {
        if (it + 1 < itc) cp_wait<1>(); else cp_wait<0>();
        __syncthreads();
        if (it + 2 < itc) {
            uint32_t s = (uint32_t)((it + 2) % 3);
            cp16(baseAH + s*ASTG + dA, pAH);
            cp16(baseAL + s*ASTG + dA, pAL);
            cp16(baseBH + s*BSTG + dB, pBH);
            cp16(baseBL + s*BSTG + dB, pBL);
            cp_commit();
            pAH += 16; pAL += 16; pBH += bstep; pBL += bstep;
        }

        uint32_t sb = (uint32_t)(it % 3);
        uint32_t aH[2][4], aL[2][4];
        #pragma unroll
        for (int mt = 0; mt < 2; mt++) {
            ldsm4(aH[mt][0], aH[mt][1], aH[mt][2], aH[mt][3], baseAH + sb*ASTG + aoff[mt]);
            ldsm4(aL[mt][0], aL[mt][1], aL[mt][2], aL[mt][3], baseAL + sb*ASTG + aoff[mt]);
        }
        #pragma unroll
        for (int grp = 0; grp < 2; grp++) {
            uint32_t bH[4][2], bL[4][2];
            #pragma unroll
            for (int pp = 0; pp < 2; pp++) {
                int p = 2*grp + pp;
                uint32_t r0, r1, r2, r3;
                if (TRANSB) ldsm4 (r0, r1, r2, r3, baseBH + sb*BSTG + boff[p]);
                else        ldsm4t(r0, r1, r2, r3, baseBH + sb*BSTG + boff[p]);
                bH[2*pp][0] = r0; bH[2*pp][1] = r1; bH[2*pp+1][0] = r2; bH[2*pp+1][1] = r3;
                if (TRANSB) ldsm4 (r0, r1, r2, r3, baseBL + sb*BSTG + boff[p]);
                else        ldsm4t(r0, r1, r2, r3, baseBL + sb*BSTG + boff[p]);
                bL[2*pp][0] = r0; bL[2*pp][1] = r1; bL[2*pp+1][0] = r2; bL[2*pp+1][1] = r3;
            }
            #pragma unroll
            for (int mt = 0; mt < 2; mt++) {
                #pragma unroll
                for (int j = 0; j < 4; j++) {
                    int nt = 4*grp + j;
                    mma_bf16(c[mt][nt], aH[mt], bH[j]);
                    mma_bf16(c[mt][nt], aH[mt], bL[j]);
                    mma_bf16(c[mt][nt], aL[mt], bH[j]);
                }
            }
        }
    }

    // ---- epilogue ----
    #pragma unroll
    for (int mt = 0; mt < 2; mt++) {
        #pragma unroll
        for (int half = 0; half < 2; half++) {
            long long row = m0 + wm + mt*16 + qr + half*8;
            #pragma unroll
            for (int nt = 0; nt < 8; nt++) {
                int col = n0 + wn + nt*8 + 2*qc;
                float v0 = c[mt][nt][half*2+0] * alpha;
                float v1 = c[mt][nt][half*2+1] * alpha;
                if (bias) { v0 += bias[col]; v1 += bias[col+1]; }
                if (act == 1) { v0 = fmaxf(v0, 0.f); v1 = fmaxf(v1, 0.f); }
                else if (act == 2) {
                    v0 = (v0 >= 0.f) ? v0 : 0.01f * v0;
                    v1 = (v1 >= 0.f) ? v1 : 0.01f * v1;
                }
                if (resid) {
                    float2 rv = *(const float2*)(resid + row*ldc + col);
                    v0 += rv.x; v1 += rv.y;
                }
                if (C) *(float2*)(C + row*ldc + col) = make_float2(v0, v1);
                if (CH) {
                    uint32_t hp, lp;
                    split_pack2(v0, v1, hp, lp);
                    *(uint32_t*)(CH + row*ldc + col) = hp;
                    *(uint32_t*)(CL + row*ldc + col) = lp;
                }
            }
        }
    }
}

// ---------------- split convert: fp32 -> hi/lo bf16 planes ----------------
__global__ void k_split(const float4* __restrict__ src,
                        uint2* __restrict__ dH, uint2* __restrict__ dL, int n4)
{
    int i = blockIdx.x * blockDim.x + threadIdx.x;
    if (i >= n4) return;
    float4 v = src[i];
    uint2 H, L;
    split_pack2(v.x, v.y, H.x, L.x);
    split_pack2(v.z, v.w, H.y, L.y);
    dH[i] = H;
    dL[i] = L;
}

// ---------------- softmax over rows of S=512 (writes split planes) --------
__global__ __launch_bounds__(256) void k_softmax(const float* __restrict__ att,
                                                 __nv_bfloat16* __restrict__ oH,
                                                 __nv_bfloat16* __restrict__ oL,
                                                 int causal)
{
    int gid = blockIdx.x;
    int i = gid & (NS - 1);
    const float* row = att + (long long)gid * NS;
    int len = causal ? (i + 1) : NS;
    int t = threadIdx.x;

    float v0 = (t       < len) ? row[t]       : -1e30f;
    float v1 = (t + 256 < len) ? row[t + 256] : -1e30f;

    __shared__ float red[8];
    float m = fmaxf(v0, v1);
    #pragma unroll
    for (int off = 16; off; off >>= 1) m = fmaxf(m, __shfl_xor_sync(0xFFFFFFFFu, m, off));
    if ((t & 31) == 0) red[t >> 5] = m;
    __syncthreads();
    float mm = red[0];
    #pragma unroll
    for (int w = 1; w < 8; w++) mm = fmaxf(mm, red[w]);
    __syncthreads();

    float e0 = (t       < len) ? __expf(v0 - mm) : 0.f;
    float e1 = (t + 256 < len) ? __expf(v1 - mm) : 0.f;
    float s = e0 + e1;
    #pragma unroll
    for (int off = 16; off; off >>= 1) s += __shfl_xor_sync(0xFFFFFFFFu, s, off);
    if ((t & 31) == 0) red[t >> 5] = s;
    __syncthreads();
    float ss = 0.f;
    #pragma unroll
    for (int w = 0; w < 8; w++) ss += red[w];
    float inv = 1.f / ss;
    e0 *= inv; e1 *= inv;

    long long base = (long long)gid * NS;
    __nv_bfloat16 h0 = __float2bfloat16_rn(e0);
    __nv_bfloat16 h1 = __float2bfloat16_rn(e1);
    oH[base + t]       = h0;
    oH[base + t + 256] = h1;
    oL[base + t]       = __float2bfloat16_rn(e0 - __bfloat162float(h0));
    oL[base + t + 256] = __float2bfloat16_rn(e1 - __bfloat162float(h1));
}

// ---------------- LayerNorm over D=1024 (in place + split planes) ---------
__global__ __launch_bounds__(256) void k_ln(float* __restrict__ h,
                                            const float* __restrict__ w,
                                            const float* __restrict__ b,
                                            __nv_bfloat16* __restrict__ oH,
                                            __nv_bfloat16* __restrict__ oL)
{
    long long base = (long long)blockIdx.x * ND;
    float* x = h + base;
    int t = threadIdx.x;
    float v[4];
    float s = 0.f;
    #pragma unroll
    for (int k = 0; k < 4; k++) { v[k] = x[t + k*256]; s += v[k]; }

    __shared__ float red[8];
    #pragma unroll
    for (int off = 16; off; off >>= 1) s += __shfl_xor_sync(0xFFFFFFFFu, s, off);
    if ((t & 31) == 0) red[t >> 5] = s;
    __syncthreads();
    float sum = 0.f;
    #pragma unroll
    for (int w2 = 0; w2 < 8; w2++) sum += red[w2];
    float mean = sum * (1.f / ND);
    __syncthreads();

    float sq = 0.f;
    #pragma unroll
    for (int k = 0; k < 4; k++) { float d = v[k] - mean; sq += d*d; }
    #pragma unroll
    for (int off = 16; off; off >>= 1) sq += __shfl_xor_sync(0xFFFFFFFFu, sq, off);
    if ((t & 31) == 0) red[t >> 5] = sq;
    __syncthreads();
    float var = 0.f;
    #pragma unroll
    for (int w2 = 0; w2 < 8; w2++) var += red[w2];
    float rstd = rsqrtf(var * (1.f / ND) + 1e-5f);

    #pragma unroll
    for (int k = 0; k < 4; k++) {
        int j = t + k*256;
        float y = (v[k] - mean) * rstd * w[j] + b[j];
        x[j] = y;
        __nv_bfloat16 hh = __float2bfloat16_rn(y);
        oH[base + j] = hh;
        oL[base + j] = __float2bfloat16_rn(y - __bfloat162float(hh));
    }
}

// ---------------- input stage: h1 = leaky(t*w1 + b1) -> split planes ------
__global__ void k_build_h1(const float* __restrict__ target,
                           const float* __restrict__ bos,
                           const float* __restrict__ w1,
                           const float* __restrict__ b1,
                           __nv_bfloat16* __restrict__ oH,
                           __nv_bfloat16* __restrict__ oL)
{
    int idx = blockIdx.x * blockDim.x + threadIdx.x;   // NB*NS*NHID
    int j = idx % NHID;
    int bs = idx / NHID;
    int s = bs % NS, bb = bs / NS;
    float t = (s == 0) ? bos[0] : target[bb*NL + s - 1];
    float v = t * w1[j] + b1[j];
    v = (v >= 0.f) ? v : 0.01f * v;
    __nv_bfloat16 hh = __float2bfloat16_rn(v);
    oH[idx] = hh;
    oL[idx] = __float2bfloat16_rn(v - __bfloat162float(hh));
}

// ---------------- fill tgt (+PE, +prev/cur) and mem ----------------
__global__ void k_fill(const float* __restrict__ gs,
                       const float* __restrict__ prev,
                       const float* __restrict__ cur,
                       float* __restrict__ h,
                       __nv_bfloat16* __restrict__ hH, __nv_bfloat16* __restrict__ hL,
                       __nv_bfloat16* __restrict__ mH, __nv_bfloat16* __restrict__ mL)
{
    int idx = blockIdx.x * blockDim.x + threadIdx.x;   // NB*NS*ND
    int j = idx % ND;
    int bs = idx / ND;
    int s = bs % NS, bb = bs / NS;
    float hv, mv;
    if (j < NHID) {
        int jj = j & ~1;
        float div = expf(-logf(10000.f) * (float)jj / (float)NHID);
        float ang = (float)s * div;
        float pe = (j & 1) ? cosf(ang) : sinf(ang);
        hv = h[idx] + pe;
        mv = gs[(long long)bs * NHID + j];
    } else if (j < NHID + NEA) {
        float p = prev[bb*NEA + (j - NHID)];
        hv = p; mv = p;
    } else {
        float c = cur[bb*NEA + (j - NHID - NEA)];
        hv = c; mv = c;
    }
    h[idx] = hv;
    __nv_bfloat16 hh = __float2bfloat16_rn(hv);
    hH[idx] = hh;
    hL[idx] = __float2bfloat16_rn(hv - __bfloat162float(hh));
    __nv_bfloat16 mh = __float2bfloat16_rn(mv);
    mH[idx] = mh;
    mL[idx] = __float2bfloat16_rn(mv - __bfloat162float(mh));
}

// ---------------- output head: dot with proj_w2, mask ----------------
__global__ void k_final(const float* __restrict__ p1,
                        const float* __restrict__ w2,
                        const float* __restrict__ b2,
                        const int* __restrict__ basis,
                        float* __restrict__ out)
{
    int warp = (blockIdx.x * blockDim.x + threadIdx.x) >> 5;
    int lane = threadIdx.x & 31;
    if (warp >= NB * NL) return;
    int bb = warp / NL, l = warp % NL;
    const float* rowp = p1 + ((long long)bb * NS + l + 1) * NHID;
    float sum = 0.f;
    #pragma unroll 4
    for (int j = lane; j < NHID; j += 32) sum += rowp[j] * w2[j];
    #pragma unroll
    for (int off = 16; off; off >>= 1) sum += __shfl_xor_sync(0xFFFFFFFFu, sum, off);
    if (lane == 0)
        out[warp] = (l < basis[bb]) ? (sum + b2[0]) : 0.f;
}

// ---------------- host side ----------------
#define SMEM_T  (12*128*16*2)                    // 49152 B  (TRANSB=true)
#define SMEM_N  (6*128*16*2 + 6*16*136*2)        // 50688 B  (TRANSB=false)

static void split_w(const float* src, __nv_bfloat16* wH, __nv_bfloat16* wL,
                    long long off, long long n)
{
    int n4 = (int)(n >> 2);
    k_split<<<(n4 + 255)/256, 256>>>((const float4*)src,
                                     (uint2*)(wH + off), (uint2*)(wL + off), n4);
}

extern "C" void kernel_launch(void* const* d_in, const int* in_sizes, int n_in,
                              void* d_out, int out_size)
{
    const float* gs      = (const float*)d_in[0];
    const float* prev    = (const float*)d_in[1];
    const float* cur     = (const float*)d_in[2];
    const float* target  = (const float*)d_in[3];
    const float* bos     = (const float*)d_in[4];
    const float* inp_w1  = (const float*)d_in[5];
    const float* inp_b1  = (const float*)d_in[6];
    const float* inp_w2  = (const float*)d_in[7];
    const float* inp_b2  = (const float*)d_in[8];
    const float* sa_qkv_w = (const float*)d_in[9];
    const float* sa_qkv_b = (const float*)d_in[10];
    const float* sa_out_w = (const float*)d_in[11];
    const float* sa_out_b = (const float*)d_in[12];
    const float* ca_qkv_w = (const float*)d_in[13];
    const float* ca_qkv_b = (const float*)d_in[14];
    const float* ca_out_w = (const float*)d_in[15];
    const float* ca_out_b = (const float*)d_in[16];
    const float* ln_w    = (const float*)d_in[17];
    const float* ln_b    = (const float*)d_in[18];
    const float* ff_w1   = (const float*)d_in[19];
    const float* ff_b1   = (const float*)d_in[20];
    const float* ff_w2   = (const float*)d_in[21];
    const float* ff_b2   = (const float*)d_in[22];
    const float* proj_w1 = (const float*)d_in[23];
    const float* proj_b1 = (const float*)d_in[24];
    const float* proj_w2 = (const float*)d_in[25];
    const float* proj_b2 = (const float*)d_in[26];
    const int*   basis   = (const int*)d_in[27];
    float* out = (float*)d_out;

    cudaFuncSetAttribute(k_gemm<true>,  cudaFuncAttributeMaxDynamicSharedMemorySize, SMEM_T);
    cudaFuncSetAttribute(k_gemm<false>, cudaFuncAttributeMaxDynamicSharedMemorySize, SMEM_N);

    float *h_, *att_, *p1_;
    __nv_bfloat16 *hH, *hL, *memH, *memL, *qkvH, *qkvL, *attH, *attL;
    __nv_bfloat16 *ffH, *ffL, *aoH, *aoL, *h1H, *h1L, *wH, *wL;
    cudaGetSymbolAddress((void**)&h_,   g_h);
    cudaGetSymbolAddress((void**)&att_, g_att);
    cudaGetSymbolAddress((void**)&p1_,  g_p1);
    cudaGetSymbolAddress((void**)&hH,   g_hH);   cudaGetSymbolAddress((void**)&hL,   g_hL);
    cudaGetSymbolAddress((void**)&memH, g_memH); cudaGetSymbolAddress((void**)&memL, g_memL);
    cudaGetSymbolAddress((void**)&qkvH, g_qkvH); cudaGetSymbolAddress((void**)&qkvL, g_qkvL);
    cudaGetSymbolAddress((void**)&attH, g_attH); cudaGetSymbolAddress((void**)&attL, g_attL);
    cudaGetSymbolAddress((void**)&ffH,  g_ffH);  cudaGetSymbolAddress((void**)&ffL,  g_ffL);
    cudaGetSymbolAddress((void**)&aoH,  g_aoH);  cudaGetSymbolAddress((void**)&aoL,  g_aoL);
    cudaGetSymbolAddress((void**)&h1H,  g_h1H);  cudaGetSymbolAddress((void**)&h1L,  g_h1L);
    cudaGetSymbolAddress((void**)&wH,   g_wH);   cudaGetSymbolAddress((void**)&wL,   g_wL);

    const int M = NB * NS;         // 8192 tokens
    const float isq = 1.f / 16.f;  // 1/sqrt(256)

    // ---- weight conversion (once per launch) ----
    split_w(sa_qkv_w, wH, wL, OFF_SAQKV, 3LL*3*ND*ND);
    split_w(ca_qkv_w, wH, wL, OFF_CAQKV, 3LL*3*ND*ND);
    split_w(sa_out_w, wH, wL, OFF_SAOUT, 3LL*ND*ND);
    split_w(ca_out_w, wH, wL, OFF_CAOUT, 3LL*ND*ND);
    split_w(ff_w1,    wH, wL, OFF_FF1,   3LL*NDFF*ND);
    split_w(ff_w2,    wH, wL, OFF_FF2,   3LL*ND*NDFF);
    split_w(inp_w2,   wH, wL, OFF_INPW2, (long long)NHID*NHID);
    split_w(proj_w1,  wH, wL, OFF_PROJ1, (long long)NHID*ND);

    // ---- input stage ----
    k_build_h1<<<(NB*NS*NHID)/256, 256>>>(target, bos, inp_w1, inp_b1, h1H, h1L);
    {
        dim3 g(NHID/128, M/128);
        k_gemm<true><<<g, 256, SMEM_T>>>(h1H, h1L, NHID, 0, 0,
                                 wH + OFF_INPW2, wL + OFF_INPW2, NHID, 0, 0,
                                 h_, nullptr, nullptr, ND, 0, 0,
                                 inp_b2, nullptr, NHID, 1, 1.f, 0, 0);
    }
    k_fill<<<(NB*NS*ND)/256, 256>>>(gs, prev, cur, h_, hH, hL, memH, memL);

    for (int l = 0; l < 3; l++) {
        long long wq = OFF_SAQKV + (long long)l * 3*ND*ND;
        long long wo = OFF_SAOUT + (long long)l * ND*ND;
        const float* qkvb = sa_qkv_b + l * 3*ND;
        const float* ob   = sa_out_b + l * ND;

        // ===== self-attention (causal) =====
        {
            dim3 g(3*ND/128, M/128);
            k_gemm<true><<<g, 256, SMEM_T>>>(hH, hL, ND, 0, 0,
                                     wH + wq, wL + wq, ND, 0, 0,
                                     nullptr, qkvH, qkvL, 3*ND, 0, 0,
                                     qkvb, nullptr, ND, 1, 1.f, 0, 0);
        }
        {
            dim3 g(NS/128, NS/128, NB*NNH);
            k_gemm<true><<<g, 256, SMEM_T>>>(qkvH, qkvL, 3*ND, (long long)NS*3*ND, NHD,
                                     qkvH + ND, qkvL + ND, 3*ND, (long long)NS*3*ND, NHD,
                                     att_, nullptr, nullptr, NS, (long long)NNH*NS*NS, (long long)NS*NS,
                                     nullptr, nullptr, NHD, NNH, isq, 0, 1);
        }
        k_softmax<<<NB*NNH*NS, 256>>>(att_, attH, attL, 1);
        {
            dim3 g(NHD/128, NS/128, NB*NNH);
            k_gemm<false><<<g, 256, SMEM_N>>>(attH, attL, NS, (long long)NNH*NS*NS, (long long)NS*NS,
                                      qkvH + 2*ND, qkvL + 2*ND, 3*ND, (long long)NS*3*ND, NHD,
                                      nullptr, aoH, aoL, ND, (long long)NS*ND, NHD,
                                      nullptr, nullptr, NS, NNH, 1.f, 0, 0);
        }
        {
            dim3 g(ND/128, M/128);
            k_gemm<true><<<g, 256, SMEM_T>>>(aoH, aoL, ND, 0, 0,
                                     wH + wo, wL + wo, ND, 0, 0,
                                     h_, nullptr, nullptr, ND, 0, 0,
                                     ob, h_, ND, 1, 1.f, 0, 0);
        }
        k_ln<<<M, 256>>>(h_, ln_w + (l*3 + 0)*ND, ln_b + (l*3 + 0)*ND, hH, hL);

        // ===== cross-attention =====
        wq = OFF_CAQKV + (long long)l * 3*ND*ND;
        wo = OFF_CAOUT + (long long)l * ND*ND;
        qkvb = ca_qkv_b + l * 3*ND;
        ob   = ca_out_b + l * ND;
        {
            dim3 g(ND/128, M/128);
            k_gemm<true><<<g, 256, SMEM_T>>>(hH, hL, ND, 0, 0,
                                     wH + wq, wL + wq, ND, 0, 0,
                                     nullptr, qkvH, qkvL, 3*ND, 0, 0,
                                     qkvb, nullptr, ND, 1, 1.f, 0, 0);
        }
        {
            dim3 g(2*ND/128, M/128);
            k_gemm<true><<<g, 256, SMEM_T>>>(memH, memL, ND, 0, 0,
                                     wH + wq + (long long)ND*ND, wL + wq + (long long)ND*ND, ND, 0, 0,
                                     nullptr, qkvH + ND, qkvL + ND, 3*ND, 0, 0,
                                     qkvb + ND, nullptr, ND, 1, 1.f, 0, 0);
        }
        {
            dim3 g(NS/128, NS/128, NB*NNH);
            k_gemm<true><<<g, 256, SMEM_T>>>(qkvH, qkvL, 3*ND, (long long)NS*3*ND, NHD,
                                     qkvH + ND, qkvL + ND, 3*ND, (long long)NS*3*ND, NHD,
                                     att_, nullptr, nullptr, NS, (long long)NNH*NS*NS, (long long)NS*NS,
                                     nullptr, nullptr, NHD, NNH, isq, 0, 0);
        }
        k_softmax<<<NB*NNH*NS, 256>>>(att_, attH, attL, 0);
        {
            dim3 g(NHD/128, NS/128, NB*NNH);
            k_gemm<false><<<g, 256, SMEM_N>>>(attH, attL, NS, (long long)NNH*NS*NS, (long long)NS*NS,
                                      qkvH + 2*ND, qkvL + 2*ND, 3*ND, (long long)NS*3*ND, NHD,
                                      nullptr, aoH, aoL, ND, (long long)NS*ND, NHD,
                                      nullptr, nullptr, NS, NNH, 1.f, 0, 0);
        }
        {
            dim3 g(ND/128, M/128);
            k_gemm<true><<<g, 256, SMEM_T>>>(aoH, aoL, ND, 0, 0,
                                     wH + wo, wL + wo, ND, 0, 0,
                                     h_, nullptr, nullptr, ND, 0, 0,
                                     ob, h_, ND, 1, 1.f, 0, 0);
        }
        k_ln<<<M, 256>>>(h_, ln_w + (l*3 + 1)*ND, ln_b + (l*3 + 1)*ND, hH, hL);

        // ===== feed-forward =====
        {
            dim3 g(NDFF/128, M/128);
            long long wf = OFF_FF1 + (long long)l*NDFF*ND;
            k_gemm<true><<<g, 256, SMEM_T>>>(hH, hL, ND, 0, 0,
                                     wH + wf, wL + wf, ND, 0, 0,
                                     nullptr, ffH, ffL, NDFF, 0, 0,
                                     ff_b1 + l*NDFF, nullptr, ND, 1, 1.f, 1, 0);
        }
        {
            dim3 g(ND/128, M/128);
            long long wf = OFF_FF2 + (long long)l*ND*NDFF;
            k_gemm<true><<<g, 256, SMEM_T>>>(ffH, ffL, NDFF, 0, 0,
                                     wH + wf, wL + wf, NDFF, 0, 0,
                                     h_, nullptr, nullptr, ND, 0, 0,
                                     ff_b2 + l*ND, h_, NDFF, 1, 1.f, 0, 0);
        }
        k_ln<<<M, 256>>>(h_, ln_w + (l*3 + 2)*ND, ln_b + (l*3 + 2)*ND, hH, hL);
    }

    // ---- output head ----
    {
        dim3 g(NHID/128, M/128);
        k_gemm<true><<<g, 256, SMEM_T>>>(hH, hL, ND, 0, 0,
                                 wH + OFF_PROJ1, wL + OFF_PROJ1, ND, 0, 0,
                                 p1_, nullptr, nullptr, NHID, 0, 0,
                                 proj_b1, nullptr, ND, 1, 1.f, 2, 0);
    }
    k_final<<<(NB*NL*32 + 255)/256, 256>>>(p1_, proj_w2, proj_b2, basis, out);
}

// round 11
// speedup vs baseline: 4.4476x; 1.0113x over previous
#include <cuda_runtime.h>
#include <cuda_bf16.h>
#include <math.h>
#include <stdint.h>

// Problem constants
#define NB   16
#define NL   511
#define NS   512
#define ND   1024
#define NHID 512
#define NDFF 2048
#define NEA  256
#define NNH  4
#define NHD  256   // head dim

// ---------------- device scratch ----------------
__device__ float g_h  [NB*NS*ND];      // residual stream (fp32)
__device__ float g_att[NB*NNH*NS*NS];  // attention scores (fp32, pre-softmax)
__device__ float g_p1 [NB*NS*NHID];

// split bf16 planes (hi / lo)
__device__ __nv_bfloat16 g_hH [NB*NS*ND],    g_hL [NB*NS*ND];
__device__ __nv_bfloat16 g_memH[NB*NS*ND],   g_memL[NB*NS*ND];
__device__ __nv_bfloat16 g_qkvH[NB*NS*3*ND], g_qkvL[NB*NS*3*ND];
__device__ __nv_bfloat16 g_attH[NB*NNH*NS*NS], g_attL[NB*NNH*NS*NS];
__device__ __nv_bfloat16 g_ffH[NB*NS*NDFF],  g_ffL[NB*NS*NDFF];
__device__ __nv_bfloat16 g_aoH[NB*NS*ND],    g_aoL[NB*NS*ND];
__device__ __nv_bfloat16 g_h1H[NB*NS*NHID],  g_h1L[NB*NS*NHID];

// weight planes (converted once per launch)
#define OFF_SAQKV  0LL
#define OFF_CAQKV  9437184LL
#define OFF_SAOUT  18874368LL
#define OFF_CAOUT  22020096LL
#define OFF_FF1    25165824LL
#define OFF_FF2    31457280LL
#define OFF_INPW2  37748736LL
#define OFF_PROJ1  38010880LL
#define W_TOTAL    38535168LL
__device__ __nv_bfloat16 g_wH[W_TOTAL], g_wL[W_TOTAL];

// ---------------- helpers ----------------
static __device__ __forceinline__ void split_pack2(float x0, float x1,
                                                   uint32_t &h, uint32_t &l)
{
    __nv_bfloat16 h0 = __float2bfloat16_rn(x0);
    __nv_bfloat16 h1 = __float2bfloat16_rn(x1);
    __nv_bfloat16 l0 = __float2bfloat16_rn(x0 - __bfloat162float(h0));
    __nv_bfloat16 l1 = __float2bfloat16_rn(x1 - __bfloat162float(h1));
    h = ((uint32_t)__bfloat16_as_ushort(h1) << 16) | (uint32_t)__bfloat16_as_ushort(h0);
    l = ((uint32_t)__bfloat16_as_ushort(l1) << 16) | (uint32_t)__bfloat16_as_ushort(l0);
}

static __device__ __forceinline__ void mma_bf16(float c[4],
    const uint32_t a[4], const uint32_t b[2])
{
    asm volatile(
        "mma.sync.aligned.m16n8k16.row.col.f32.bf16.bf16.f32 "
        "{%0,%1,%2,%3},{%4,%5,%6,%7},{%8,%9},{%0,%1,%2,%3};"
        : "+f"(c[0]), "+f"(c[1]), "+f"(c[2]), "+f"(c[3])
        : "r"(a[0]), "r"(a[1]), "r"(a[2]), "r"(a[3]), "r"(b[0]), "r"(b[1]));
}

static __device__ __forceinline__ void ldsm4(uint32_t &r0, uint32_t &r1,
                                             uint32_t &r2, uint32_t &r3, uint32_t a)
{
    asm volatile("ldmatrix.sync.aligned.m8n8.x4.shared.b16 {%0,%1,%2,%3},[%4];"
        : "=r"(r0), "=r"(r1), "=r"(r2), "=r"(r3) : "r"(a));
}

static __device__ __forceinline__ void ldsm4t(uint32_t &r0, uint32_t &r1,
                                              uint32_t &r2, uint32_t &r3, uint32_t a)
{
    asm volatile("ldmatrix.sync.aligned.m8n8.x4.trans.shared.b16 {%0,%1,%2,%3},[%4];"
        : "=r"(r0), "=r"(r1), "=r"(r2), "=r"(r3) : "r"(a));
}

static __device__ __forceinline__ void cp16(uint32_t dst, const void* src)
{
    asm volatile("cp.async.cg.shared.global [%0], [%1], 16;" :: "r"(dst), "l"(src));
}
static __device__ __forceinline__ void cp_commit()
{
    asm volatile("cp.async.commit_group;");
}
template<int N> static __device__ __forceinline__ void cp_wait()
{
    asm volatile("cp.async.wait_group %0;" :: "n"(N));
}

// swizzled byte offset within a [rows x 32 elems] bf16 stage: 64B rows, 4x16B
// chunks, chunk XOR'd with (row>>1)&3 -> every 8-row x one-chunk ldmatrix read
// covers all 32 banks exactly once.
static __device__ __forceinline__ uint32_t swz32(int row, int ch)
{
    return (uint32_t)(row * 64 + ((ch ^ ((row >> 1) & 3)) << 4));
}

// ---------------- tensor-core tiled GEMM (bf16x3 emulated fp32) -------------
// C = act(alpha * A @ op(B) + bias) [+ resid]  and/or split-bf16 planes CH/CL.
// A,B pre-split bf16 hi/lo planes. Tile 128x128, kstep 32, THREE-stage
// cp.async pipeline (ONE __syncthreads per 96-MMA iter), 8 warps (4M x 2N),
// warp tile 32x64, mma m16n8k16, 2 CTAs/SM.
// TRANSB=true : op(B)=B^T, B is [N,K] row-major.  TRANSB=false: B is [K,N].
// Requires K % 32 == 0.
template<bool TRANSB>
__global__ __launch_bounds__(256, 2) void k_gemm(
    const __nv_bfloat16* __restrict__ AH, const __nv_bfloat16* __restrict__ AL,
    int lda, long long strAb, long long strAh,
    const __nv_bfloat16* __restrict__ BH, const __nv_bfloat16* __restrict__ BL,
    int ldb, long long strBb, long long strBh,
    float* __restrict__ C, __nv_bfloat16* __restrict__ CH, __nv_bfloat16* __restrict__ CL,
    int ldc, long long strCb, long long strCh,
    const float* __restrict__ bias, const float* __restrict__ resid,
    int K, int nh, float alpha, int act, int causal)
{
    int z = blockIdx.z;
    int zb = z / nh, zh = z % nh;
    AH += zb*strAb + zh*strAh;  AL += zb*strAb + zh*strAh;
    BH += zb*strBb + zh*strBh;  BL += zb*strBb + zh*strBh;
    long long coff = zb*strCb + zh*strCh;
    if (C)  C  += coff;
    if (CH) { CH += coff; CL += coff; }

    int m0 = blockIdx.y * 128, n0 = blockIdx.x * 128;
    if (causal && n0 > m0) return;   // fully-masked tile

    extern __shared__ char sdyn[];
    constexpr uint32_t ASTG = 128*32*2;                       // 8192 B per A stage
    constexpr uint32_t BSTG = TRANSB ? 128*32*2 : 32*136*2;   // B stage bytes
    uint32_t base   = (uint32_t)__cvta_generic_to_shared(sdyn);
    uint32_t baseAH = base;
    uint32_t baseAL = base + 3*ASTG;
    uint32_t baseBH = base + 6*ASTG;
    uint32_t baseBL = base + 6*ASTG + 3*BSTG;

    int tid  = threadIdx.x;
    int lane = tid & 31;
    int wid  = tid >> 5;
    int wm = (wid & 3) * 32;
    int wn = (wid >> 2) * 64;
    int qr = lane >> 2;
    int qc = lane & 3;

    // loader indices
    int arow = tid >> 1;            // 0..127
    int ach  = tid & 1;             // chunk pair: (ach, ach+2)
    int bkr  = tid >> 4;            // 0..15   (non-T: k rows bkr, bkr+16)
    int bch  = tid & 15;            // 0..15   (non-T: 16B chunk along n)

    uint32_t dA0 = swz32(arow, ach);
    uint32_t dA1 = swz32(arow, ach + 2);
    uint32_t dB0, dB1;
    if (TRANSB) { dB0 = dA0; dB1 = dA1; }
    else {
        dB0 = (uint32_t)((bkr*136 + bch*8) * 2);
        dB1 = (uint32_t)(((bkr+16)*136 + bch*8) * 2);
    }

    // running global pointers (first chunk; second chunk at fixed delta)
    const __nv_bfloat16 *pAH = AH + (long long)(m0 + arow)*lda + ach*8;
    const __nv_bfloat16 *pAL = AL + (long long)(m0 + arow)*lda + ach*8;
    const __nv_bfloat16 *pBH, *pBL;
    long long gB1;                   // elems between B chunk0 and chunk1
    if (TRANSB) {
        pBH = BH + (long long)(n0 + arow)*ldb + ach*8;
        pBL = BL + (long long)(n0 + arow)*ldb + ach*8;
        gB1 = 16;
    } else {
        pBH = BH + (long long)bkr*ldb + n0 + bch*8;
        pBL = BL + (long long)bkr*ldb + n0 + bch*8;
        gB1 = (long long)16*ldb;
    }
    long long bstep = TRANSB ? 32 : (long long)32*ldb;

    // fragment read offsets (loop-invariant)
    uint32_t aoff[2][2];
    #pragma unroll
    for (int mt = 0; mt < 2; mt++)
        #pragma unroll
        for (int s = 0; s < 2; s++)
            aoff[mt][s] = swz32(wm + mt*16 + (lane & 15), 2*s + (lane >> 4));

    uint32_t boff[4][2];
    #pragma unroll
    for (int p = 0; p < 4; p++) {
        #pragma unroll
        for (int s = 0; s < 2; s++) {
            if (TRANSB) {
                int rr = wn + p*16 + ((lane >> 4) << 3) + (lane & 7);
                boff[p][s] = swz32(rr, 2*s + ((lane >> 3) & 1));
            } else {
                int rk = 16*s + (((lane >> 3) & 1) << 3) + (lane & 7);
                int cn = wn + p*16 + ((lane >> 4) << 3);
                boff[p][s] = (uint32_t)((rk * 136 + cn) * 2);
            }
        }
    }

    float c[2][8][4];
    #pragma unroll
    for (int i = 0; i < 2; i++)
        #pragma unroll
        for (int j = 0; j < 8; j++)
            #pragma unroll
            for (int t = 0; t < 4; t++) c[i][j][t] = 0.f;

    int itc = K >> 5;

    // prologue: issue stages 0 and 1
    #pragma unroll
    for (int s = 0; s < 2; s++) {
        cp16(baseAH + s*ASTG + dA0, pAH);      cp16(baseAH + s*ASTG + dA1, pAH + 16);
        cp16(baseAL + s*ASTG + dA0, pAL);      cp16(baseAL + s*ASTG + dA1, pAL + 16);
        cp16(baseBH + s*BSTG + dB0, pBH);      cp16(baseBH + s*BSTG + dB1, pBH + gB1);
        cp16(baseBL + s*BSTG + dB0, pBL);      cp16(baseBL + s*BSTG + dB1, pBL + gB1);
        cp_commit();
        pAH += 32; pAL += 32; pBH += bstep; pBL += bstep;
    }

    for (int it = 0; it < itc; it++) {
        if (it + 1 < itc) cp_wait<1>(); else cp_wait<0>();
        __syncthreads();
        if (it + 2 < itc) {
            uint32_t s = (uint32_t)((it + 2) % 3);
            cp16(baseAH + s*ASTG + dA0, pAH);  cp16(baseAH + s*ASTG + dA1, pAH + 16);
            cp16(baseAL + s*ASTG + dA0, pAL);  cp16(baseAL + s*ASTG + dA1, pAL + 16);
            cp16(baseBH + s*BSTG + dB0, pBH);  cp16(baseBH + s*BSTG + dB1, pBH + gB1);
            cp16(baseBL + s*BSTG + dB0, pBL);  cp16(baseBL + s*BSTG + dB1, pBL + gB1);
            cp_commit();
            pAH += 32; pAL += 32; pBH += bstep; pBL += bstep;
        }

        uint32_t sb = (uint32_t)(it % 3);
        #pragma unroll
        for (int s = 0; s < 2; s++) {
            uint32_t aH[2][4], aL[2][4];
            #pragma unroll
            for (int mt = 0; mt < 2; mt++) {
                ldsm4(aH[mt][0], aH[mt][1], aH[mt][2], aH[mt][3],
                      baseAH + sb*ASTG + aoff[mt][s]);
                ldsm4(aL[mt][0], aL[mt][1], aL[mt][2], aL[mt][3],
                      baseAL + sb*ASTG + aoff[mt][s]);
            }
            #pragma unroll
            for (int grp = 0; grp < 2; grp++) {
                uint32_t bH[4][2], bL[4][2];
                #pragma unroll
                for (int pp = 0; pp < 2; pp++) {
                    int p = 2*grp + pp;
                    uint32_t r0, r1, r2, r3;
                    if (TRANSB) ldsm4 (r0, r1, r2, r3, baseBH + sb*BSTG + boff[p][s]);
                    else        ldsm4t(r0, r1, r2, r3, baseBH + sb*BSTG + boff[p][s]);
                    bH[2*pp][0] = r0; bH[2*pp][1] = r1; bH[2*pp+1][0] = r2; bH[2*pp+1][1] = r3;
                    if (TRANSB) ldsm4 (r0, r1, r2, r3, baseBL + sb*BSTG + boff[p][s]);
                    else        ldsm4t(r0, r1, r2, r3, baseBL + sb*BSTG + boff[p][s]);
                    bL[2*pp][0] = r0; bL[2*pp][1] = r1; bL[2*pp+1][0] = r2; bL[2*pp+1][1] = r3;
                }
                #pragma unroll
                for (int mt = 0; mt < 2; mt++) {
                    #pragma unroll
                    for (int j = 0; j < 4; j++) {
                        int nt = 4*grp + j;
                        mma_bf16(c[mt][nt], aH[mt], bH[j]);
                        mma_bf16(c[mt][nt], aH[mt], bL[j]);
                        mma_bf16(c[mt][nt], aL[mt], bH[j]);
                    }
                }
            }
        }
    }

    // ---- epilogue ----
    #pragma unroll
    for (int mt = 0; mt < 2; mt++) {
        #pragma unroll
        for (int half = 0; half < 2; half++) {
            long long row = m0 + wm + mt*16 + qr + half*8;
            #pragma unroll
            for (int nt = 0; nt < 8; nt++) {
                int col = n0 + wn + nt*8 + 2*qc;
                float v0 = c[mt][nt][half*2+0] * alpha;
                float v1 = c[mt][nt][half*2+1] * alpha;
                if (bias) { v0 += bias[col]; v1 += bias[col+1]; }
                if (act == 1) { v0 = fmaxf(v0, 0.f); v1 = fmaxf(v1, 0.f); }
                else if (act == 2) {
                    v0 = (v0 >= 0.f) ? v0 : 0.01f * v0;
                    v1 = (v1 >= 0.f) ? v1 : 0.01f * v1;
                }
                if (resid) {
                    float2 rv = *(const float2*)(resid + row*ldc + col);
                    v0 += rv.x; v1 += rv.y;
                }
                if (C) *(float2*)(C + row*ldc + col) = make_float2(v0, v1);
                if (CH) {
                    uint32_t hp, lp;
                    split_pack2(v0, v1, hp, lp);
                    *(uint32_t*)(CH + row*ldc + col) = hp;
                    *(uint32_t*)(CL + row*ldc + col) = lp;
                }
            }
        }
    }
}

// ---------------- split convert: fp32 -> hi/lo bf16 planes ----------------
__global__ void k_split(const float4* __restrict__ src,
                        uint2* __restrict__ dH, uint2* __restrict__ dL, int n4)
{
    int i = blockIdx.x * blockDim.x + threadIdx.x;
    if (i >= n4) return;
    float4 v = src[i];
    uint2 H, L;
    split_pack2(v.x, v.y, H.x, L.x);
    split_pack2(v.z, v.w, H.y, L.y);
    dH[i] = H;
    dL[i] = L;
}

// ---------------- softmax over rows of S=512 (writes split planes) --------
__global__ __launch_bounds__(256) void k_softmax(const float* __restrict__ att,
                                                 __nv_bfloat16* __restrict__ oH,
                                                 __nv_bfloat16* __restrict__ oL,
                                                 int causal)
{
    int gid = blockIdx.x;
    int i = gid & (NS - 1);
    const float* row = att + (long long)gid * NS;
    int len = causal ? (i + 1) : NS;
    int t = threadIdx.x;

    float v0 = (t       < len) ? row[t]       : -1e30f;
    float v1 = (t + 256 < len) ? row[t + 256] : -1e30f;

    __shared__ float red[8];
    float m = fmaxf(v0, v1);
    #pragma unroll
    for (int off = 16; off; off >>= 1) m = fmaxf(m, __shfl_xor_sync(0xFFFFFFFFu, m, off));
    if ((t & 31) == 0) red[t >> 5] = m;
    __syncthreads();
    float mm = red[0];
    #pragma unroll
    for (int w = 1; w < 8; w++) mm = fmaxf(mm, red[w]);
    __syncthreads();

    float e0 = (t       < len) ? __expf(v0 - mm) : 0.f;
    float e1 = (t + 256 < len) ? __expf(v1 - mm) : 0.f;
    float s = e0 + e1;
    #pragma unroll
    for (int off = 16; off; off >>= 1) s += __shfl_xor_sync(0xFFFFFFFFu, s, off);
    if ((t & 31) == 0) red[t >> 5] = s;
    __syncthreads();
    float ss = 0.f;
    #pragma unroll
    for (int w = 0; w < 8; w++) ss += red[w];
    float inv = 1.f / ss;
    e0 *= inv; e1 *= inv;

    long long base = (long long)gid * NS;
    __nv_bfloat16 h0 = __float2bfloat16_rn(e0);
    __nv_bfloat16 h1 = __float2bfloat16_rn(e1);
    oH[base + t]       = h0;
    oH[base + t + 256] = h1;
    oL[base + t]       = __float2bfloat16_rn(e0 - __bfloat162float(h0));
    oL[base + t + 256] = __float2bfloat16_rn(e1 - __bfloat162float(h1));
}

// ---------------- LayerNorm over D=1024 (in place + split planes) ---------
__global__ __launch_bounds__(256) void k_ln(float* __restrict__ h,
                                            const float* __restrict__ w,
                                            const float* __restrict__ b,
                                            __nv_bfloat16* __restrict__ oH,
                                            __nv_bfloat16* __restrict__ oL)
{
    long long base = (long long)blockIdx.x * ND;
    float* x = h + base;
    int t = threadIdx.x;
    float v[4];
    float s = 0.f;
    #pragma unroll
    for (int k = 0; k < 4; k++) { v[k] = x[t + k*256]; s += v[k]; }

    __shared__ float red[8];
    #pragma unroll
    for (int off = 16; off; off >>= 1) s += __shfl_xor_sync(0xFFFFFFFFu, s, off);
    if ((t & 31) == 0) red[t >> 5] = s;
    __syncthreads();
    float sum = 0.f;
    #pragma unroll
    for (int w2 = 0; w2 < 8; w2++) sum += red[w2];
    float mean = sum * (1.f / ND);
    __syncthreads();

    float sq = 0.f;
    #pragma unroll
    for (int k = 0; k < 4; k++) { float d = v[k] - mean; sq += d*d; }
    #pragma unroll
    for (int off = 16; off; off >>= 1) sq += __shfl_xor_sync(0xFFFFFFFFu, sq, off);
    if ((t & 31) == 0) red[t >> 5] = sq;
    __syncthreads();
    float var = 0.f;
    #pragma unroll
    for (int w2 = 0; w2 < 8; w2++) var += red[w2];
    float rstd = rsqrtf(var * (1.f / ND) + 1e-5f);

    #pragma unroll
    for (int k = 0; k < 4; k++) {
        int j = t + k*256;
        float y = (v[k] - mean) * rstd * w[j] + b[j];
        x[j] = y;
        __nv_bfloat16 hh = __float2bfloat16_rn(y);
        oH[base + j] = hh;
        oL[base + j] = __float2bfloat16_rn(y - __bfloat162float(hh));
    }
}

// ---------------- input stage: h1 = leaky(t*w1 + b1) -> split planes ------
__global__ void k_build_h1(const float* __restrict__ target,
                           const float* __restrict__ bos,
                           const float* __restrict__ w1,
                           const float* __restrict__ b1,
                           __nv_bfloat16* __restrict__ oH,
                           __nv_bfloat16* __restrict__ oL)
{
    int idx = blockIdx.x * blockDim.x + threadIdx.x;   // NB*NS*NHID
    int j = idx % NHID;
    int bs = idx / NHID;
    int s = bs % NS, bb = bs / NS;
    float t = (s == 0) ? bos[0] : target[bb*NL + s - 1];
    float v = t * w1[j] + b1[j];
    v = (v >= 0.f) ? v : 0.01f * v;
    __nv_bfloat16 hh = __float2bfloat16_rn(v);
    oH[idx] = hh;
    oL[idx] = __float2bfloat16_rn(v - __bfloat162float(hh));
}

// ---------------- fill tgt (+PE, +prev/cur) and mem ----------------
__global__ void k_fill(const float* __restrict__ gs,
                       const float* __restrict__ prev,
                       const float* __restrict__ cur,
                       float* __restrict__ h,
                       __nv_bfloat16* __restrict__ hH, __nv_bfloat16* __restrict__ hL,
                       __nv_bfloat16* __restrict__ mH, __nv_bfloat16* __restrict__ mL)
{
    int idx = blockIdx.x * blockDim.x + threadIdx.x;   // NB*NS*ND
    int j = idx % ND;
    int bs = idx / ND;
    int s = bs % NS, bb = bs / NS;
    float hv, mv;
    if (j < NHID) {
        int jj = j & ~1;
        float div = expf(-logf(10000.f) * (float)jj / (float)NHID);
        float ang = (float)s * div;
        float pe = (j & 1) ? cosf(ang) : sinf(ang);
        hv = h[idx] + pe;
        mv = gs[(long long)bs * NHID + j];
    } else if (j < NHID + NEA) {
        float p = prev[bb*NEA + (j - NHID)];
        hv = p; mv = p;
    } else {
        float c = cur[bb*NEA + (j - NHID - NEA)];
        hv = c; mv = c;
    }
    h[idx] = hv;
    __nv_bfloat16 hh = __float2bfloat16_rn(hv);
    hH[idx] = hh;
    hL[idx] = __float2bfloat16_rn(hv - __bfloat162float(hh));
    __nv_bfloat16 mh = __float2bfloat16_rn(mv);
    mH[idx] = mh;
    mL[idx] = __float2bfloat16_rn(mv - __bfloat162float(mh));
}

// ---------------- output head: dot with proj_w2, mask ----------------
__global__ void k_final(const float* __restrict__ p1,
                        const float* __restrict__ w2,
                        const float* __restrict__ b2,
                        const int* __restrict__ basis,
                        float* __restrict__ out)
{
    int warp = (blockIdx.x * blockDim.x + threadIdx.x) >> 5;
    int lane = threadIdx.x & 31;
    if (warp >= NB * NL) return;
    int bb = warp / NL, l = warp % NL;
    const float* rowp = p1 + ((long long)bb * NS + l + 1) * NHID;
    float sum = 0.f;
    #pragma unroll 4
    for (int j = lane; j < NHID; j += 32) sum += rowp[j] * w2[j];
    #pragma unroll
    for (int off = 16; off; off >>= 1) sum += __shfl_xor_sync(0xFFFFFFFFu, sum, off);
    if (lane == 0)
        out[warp] = (l < basis[bb]) ? (sum + b2[0]) : 0.f;
}

// ---------------- host side ----------------
#define SMEM_T  (12*128*32*2)                    // 98304 B  (TRANSB=true)
#define SMEM_N  (6*128*32*2 + 6*32*136*2)        // 101376 B (TRANSB=false)

static void split_w(const float* src, __nv_bfloat16* wH, __nv_bfloat16* wL,
                    long long off, long long n)
{
    int n4 = (int)(n >> 2);
    k_split<<<(n4 + 255)/256, 256>>>((const float4*)src,
                                     (uint2*)(wH + off), (uint2*)(wL + off), n4);
}

extern "C" void kernel_launch(void* const* d_in, const int* in_sizes, int n_in,
                              void* d_out, int out_size)
{
    const float* gs      = (const float*)d_in[0];
    const float* prev    = (const float*)d_in[1];
    const float* cur     = (const float*)d_in[2];
    const float* target  = (const float*)d_in[3];
    const float* bos     = (const float*)d_in[4];
    const float* inp_w1  = (const float*)d_in[5];
    const float* inp_b1  = (const float*)d_in[6];
    const float* inp_w2  = (const float*)d_in[7];
    const float* inp_b2  = (const float*)d_in[8];
    const float* sa_qkv_w = (const float*)d_in[9];
    const float* sa_qkv_b = (const float*)d_in[10];
    const float* sa_out_w = (const float*)d_in[11];
    const float* sa_out_b = (const float*)d_in[12];
    const float* ca_qkv_w = (const float*)d_in[13];
    const float* ca_qkv_b = (const float*)d_in[14];
    const float* ca_out_w = (const float*)d_in[15];
    const float* ca_out_b = (const float*)d_in[16];
    const float* ln_w    = (const float*)d_in[17];
    const float* ln_b    = (const float*)d_in[18];
    const float* ff_w1   = (const float*)d_in[19];
    const float* ff_b1   = (const float*)d_in[20];
    const float* ff_w2   = (const float*)d_in[21];
    const float* ff_b2   = (const float*)d_in[22];
    const float* proj_w1 = (const float*)d_in[23];
    const float* proj_b1 = (const float*)d_in[24];
    const float* proj_w2 = (const float*)d_in[25];
    const float* proj_b2 = (const float*)d_in[26];
    const int*   basis   = (const int*)d_in[27];
    float* out = (float*)d_out;

    cudaFuncSetAttribute(k_gemm<true>,  cudaFuncAttributeMaxDynamicSharedMemorySize, SMEM_T);
    cudaFuncSetAttribute(k_gemm<false>, cudaFuncAttributeMaxDynamicSharedMemorySize, SMEM_N);

    float *h_, *att_, *p1_;
    __nv_bfloat16 *hH, *hL, *memH, *memL, *qkvH, *qkvL, *attH, *attL;
    __nv_bfloat16 *ffH, *ffL, *aoH, *aoL, *h1H, *h1L, *wH, *wL;
    cudaGetSymbolAddress((void**)&h_,   g_h);
    cudaGetSymbolAddress((void**)&att_, g_att);
    cudaGetSymbolAddress((void**)&p1_,  g_p1);
    cudaGetSymbolAddress((void**)&hH,   g_hH);   cudaGetSymbolAddress((void**)&hL,   g_hL);
    cudaGetSymbolAddress((void**)&memH, g_memH); cudaGetSymbolAddress((void**)&memL, g_memL);
    cudaGetSymbolAddress((void**)&qkvH, g_qkvH); cudaGetSymbolAddress((void**)&qkvL, g_qkvL);
    cudaGetSymbolAddress((void**)&attH, g_attH); cudaGetSymbolAddress((void**)&attL, g_attL);
    cudaGetSymbolAddress((void**)&ffH,  g_ffH);  cudaGetSymbolAddress((void**)&ffL,  g_ffL);
    cudaGetSymbolAddress((void**)&aoH,  g_aoH);  cudaGetSymbolAddress((void**)&aoL,  g_aoL);
    cudaGetSymbolAddress((void**)&h1H,  g_h1H);  cudaGetSymbolAddress((void**)&h1L,  g_h1L);
    cudaGetSymbolAddress((void**)&wH,   g_wH);   cudaGetSymbolAddress((void**)&wL,   g_wL);

    const int M = NB * NS;         // 8192 tokens
    const float isq = 1.f / 16.f;  // 1/sqrt(256)

    // ---- weight conversion (once per launch) ----
    split_w(sa_qkv_w, wH, wL, OFF_SAQKV, 3LL*3*ND*ND);
    split_w(ca_qkv_w, wH, wL, OFF_CAQKV, 3LL*3*ND*ND);
    split_w(sa_out_w, wH, wL, OFF_SAOUT, 3LL*ND*ND);
    split_w(ca_out_w, wH, wL, OFF_CAOUT, 3LL*ND*ND);
    split_w(ff_w1,    wH, wL, OFF_FF1,   3LL*NDFF*ND);
    split_w(ff_w2,    wH, wL, OFF_FF2,   3LL*ND*NDFF);
    split_w(inp_w2,   wH, wL, OFF_INPW2, (long long)NHID*NHID);
    split_w(proj_w1,  wH, wL, OFF_PROJ1, (long long)NHID*ND);

    // ---- input stage ----
    k_build_h1<<<(NB*NS*NHID)/256, 256>>>(target, bos, inp_w1, inp_b1, h1H, h1L);
    {
        dim3 g(NHID/128, M/128);
        k_gemm<true><<<g, 256, SMEM_T>>>(h1H, h1L, NHID, 0, 0,
                                 wH + OFF_INPW2, wL + OFF_INPW2, NHID, 0, 0,
                                 h_, nullptr, nullptr, ND, 0, 0,
                                 inp_b2, nullptr, NHID, 1, 1.f, 0, 0);
    }
    k_fill<<<(NB*NS*ND)/256, 256>>>(gs, prev, cur, h_, hH, hL, memH, memL);

    for (int l = 0; l < 3; l++) {
        long long wq = OFF_SAQKV + (long long)l * 3*ND*ND;
        long long wo = OFF_SAOUT + (long long)l * ND*ND;
        const float* qkvb = sa_qkv_b + l * 3*ND;
        const float* ob   = sa_out_b + l * ND;

        // ===== self-attention (causal) =====
        {
            dim3 g(3*ND/128, M/128);
            k_gemm<true><<<g, 256, SMEM_T>>>(hH, hL, ND, 0, 0,
                                     wH + wq, wL + wq, ND, 0, 0,
                                     nullptr, qkvH, qkvL, 3*ND, 0, 0,
                                     qkvb, nullptr, ND, 1, 1.f, 0, 0);
        }
        {
            dim3 g(NS/128, NS/128, NB*NNH);
            k_gemm<true><<<g, 256, SMEM_T>>>(qkvH, qkvL, 3*ND, (long long)NS*3*ND, NHD,
                                     qkvH + ND, qkvL + ND, 3*ND, (long long)NS*3*ND, NHD,
                                     att_, nullptr, nullptr, NS, (long long)NNH*NS*NS, (long long)NS*NS,
                                     nullptr, nullptr, NHD, NNH, isq, 0, 1);
        }
        k_softmax<<<NB*NNH*NS, 256>>>(att_, attH, attL, 1);
        {
            dim3 g(NHD/128, NS/128, NB*NNH);
            k_gemm<false><<<g, 256, SMEM_N>>>(attH, attL, NS, (long long)NNH*NS*NS, (long long)NS*NS,
                                      qkvH + 2*ND, qkvL + 2*ND, 3*ND, (long long)NS*3*ND, NHD,
                                      nullptr, aoH, aoL, ND, (long long)NS*ND, NHD,
                                      nullptr, nullptr, NS, NNH, 1.f, 0, 0);
        }
        {
            dim3 g(ND/128, M/128);
            k_gemm<true><<<g, 256, SMEM_T>>>(aoH, aoL, ND, 0, 0,
                                     wH + wo, wL + wo, ND, 0, 0,
                                     h_, nullptr, nullptr, ND, 0, 0,
                                     ob, h_, ND, 1, 1.f, 0, 0);
        }
        k_ln<<<M, 256>>>(h_, ln_w + (l*3 + 0)*ND, ln_b + (l*3 + 0)*ND, hH, hL);

        // ===== cross-attention =====
        wq = OFF_CAQKV + (long long)l * 3*ND*ND;
        wo = OFF_CAOUT + (long long)l * ND*ND;
        qkvb = ca_qkv_b + l * 3*ND;
        ob   = ca_out_b + l * ND;
        {
            dim3 g(ND/128, M/128);
            k_gemm<true><<<g, 256, SMEM_T>>>(hH, hL, ND, 0, 0,
                                     wH + wq, wL + wq, ND, 0, 0,
                                     nullptr, qkvH, qkvL, 3*ND, 0, 0,
                                     qkvb, nullptr, ND, 1, 1.f, 0, 0);
        }
        {
            dim3 g(2*ND/128, M/128);
            k_gemm<true><<<g, 256, SMEM_T>>>(memH, memL, ND, 0, 0,
                                     wH + wq + (long long)ND*ND, wL + wq + (long long)ND*ND, ND, 0, 0,
                                     nullptr, qkvH + ND, qkvL + ND, 3*ND, 0, 0,
                                     qkvb + ND, nullptr, ND, 1, 1.f, 0, 0);
        }
        {
            dim3 g(NS/128, NS/128, NB*NNH);
            k_gemm<true><<<g, 256, SMEM_T>>>(qkvH, qkvL, 3*ND, (long long)NS*3*ND, NHD,
                                     qkvH + ND, qkvL + ND, 3*ND, (long long)NS*3*ND, NHD,
                                     att_, nullptr, nullptr, NS, (long long)NNH*NS*NS, (long long)NS*NS,
                                     nullptr, nullptr, NHD, NNH, isq, 0, 0);
        }
        k_softmax<<<NB*NNH*NS, 256>>>(att_, attH, attL, 0);
        {
            dim3 g(NHD/128, NS/128, NB*NNH);
            k_gemm<false><<<g, 256, SMEM_N>>>(attH, attL, NS, (long long)NNH*NS*NS, (long long)NS*NS,
                                      qkvH + 2*ND, qkvL + 2*ND, 3*ND, (long long)NS*3*ND, NHD,
                                      nullptr, aoH, aoL, ND, (long long)NS*ND, NHD,
                                      nullptr, nullptr, NS, NNH, 1.f, 0, 0);
        }
        {
            dim3 g(ND/128, M/128);
            k_gemm<true><<<g, 256, SMEM_T>>>(aoH, aoL, ND, 0, 0,
                                     wH + wo, wL + wo, ND, 0, 0,
                                     h_, nullptr, nullptr, ND, 0, 0,
                                     ob, h_, ND, 1, 1.f, 0, 0);
        }
        k_ln<<<M, 256>>>(h_, ln_w + (l*3 + 1)*ND, ln_b + (l*3 + 1)*ND, hH, hL);

        // ===== feed-forward =====
        {
            dim3 g(NDFF/128, M/128);
            long long wf = OFF_FF1 + (long long)l*NDFF*ND;
            k_gemm<true><<<g, 256, SMEM_T>>>(hH, hL, ND, 0, 0,
                                     wH + wf, wL + wf, ND, 0, 0,
                                     nullptr, ffH, ffL, NDFF, 0, 0,
                                     ff_b1 + l*NDFF, nullptr, ND, 1, 1.f, 1, 0);
        }
        {
            dim3 g(ND/128, M/128);
            long long wf = OFF_FF2 + (long long)l*ND*NDFF;
            k_gemm<true><<<g, 256, SMEM_T>>>(ffH, ffL, NDFF, 0, 0,
                                     wH + wf, wL + wf, NDFF, 0, 0,
                                     h_, nullptr, nullptr, ND, 0, 0,
                                     ff_b2 + l*ND, h_, NDFF, 1, 1.f, 0, 0);
        }
        k_ln<<<M, 256>>>(h_, ln_w + (l*3 + 2)*ND, ln_b + (l*3 + 2)*ND, hH, hL);
    }

    // ---- output head ----
    {
        dim3 g(NHID/128, M/128);
        k_gemm<true><<<g, 256, SMEM_T>>>(hH, hL, ND, 0, 0,
                                 wH + OFF_PROJ1, wL + OFF_PROJ1, ND, 0, 0,
                                 p1_, nullptr, nullptr, NHID, 0, 0,
                                 proj_b1, nullptr, ND, 1, 1.f, 2, 0);
    }
    k_final<<<(NB*NL*32 + 255)/256, 256>>>(p1_, proj_w2, proj_b2, basis, out);
}